// round 4
// baseline (speedup 1.0000x reference)
#include <cuda_runtime.h>
#include <cfloat>
#include <stdint.h>

#define N_NODES 100000
#define N_EDGES 1600000
#define BGRAPH  64
#define DINP    9
#define H       128
#define EPS     1e-5f

#define SCAN_BLK 512
#define SCAN_NB  196   // ceil(100000/512)
#define POOL_CH  16

typedef unsigned long long ull;

// ---------------- scratch (device globals; no allocation allowed) -----------
__device__ float g_hA[N_NODES * H];
__device__ float g_hB[N_NODES * H];
__device__ float g_Wt[3 * 256 * H];     // per-layer [256][128] = [Wl;Wr] transposed
__device__ int   g_rowptr[N_NODES + 1];
__device__ int   g_col[N_EDGES];
__device__ int   g_deg[N_NODES];
__device__ int   g_cursor[N_NODES];
__device__ int   g_bsum[SCAN_NB];
__device__ int   g_start[BGRAPH + 1];
__device__ float g_pp[BGRAPH * POOL_CH * 2 * H];

// ---------------- f32x2 helpers (Blackwell packed fp32) ---------------------
__device__ __forceinline__ ull pack2(float v) {
    ull r;
    unsigned u = __float_as_uint(v);
    asm("mov.b64 %0, {%1, %2};" : "=l"(r) : "r"(u), "r"(u));
    return r;
}
#define FMA2(d, a, b) asm("fma.rn.f32x2 %0, %1, %2, %0;" : "+l"(d) : "l"(a), "l"(b))

__device__ __forceinline__ float f2lo(ull v) {
    return __uint_as_float((unsigned)(v & 0xffffffffull));
}
__device__ __forceinline__ float f2hi(ull v) {
    return __uint_as_float((unsigned)(v >> 32));
}

// ---------------- CSR build -------------------------------------------------
__global__ void k_zero() {
    int i = blockIdx.x * blockDim.x + threadIdx.x;
    if (i < N_NODES) { g_deg[i] = 0; g_cursor[i] = 0; }
}

__global__ void k_deg(const int* __restrict__ dst) {
    int e = blockIdx.x * blockDim.x + threadIdx.x;
    if (e < N_EDGES) atomicAdd(&g_deg[dst[e]], 1);
}

__global__ void k_scan1() {
    __shared__ int sh[SCAN_BLK];
    int t = threadIdx.x;
    int i = blockIdx.x * SCAN_BLK + t;
    int v = (i < N_NODES) ? g_deg[i] : 0;
    sh[t] = v; __syncthreads();
    for (int o = 1; o < SCAN_BLK; o <<= 1) {
        int a = (t >= o) ? sh[t - o] : 0;
        __syncthreads();
        sh[t] += a;
        __syncthreads();
    }
    if (i < N_NODES) g_rowptr[i] = sh[t] - v;   // local exclusive
    if (t == SCAN_BLK - 1) g_bsum[blockIdx.x] = sh[t];
}

__global__ void k_scan2() {
    __shared__ int sh[256];
    int t = threadIdx.x;
    int v = (t < SCAN_NB) ? g_bsum[t] : 0;
    sh[t] = v; __syncthreads();
    for (int o = 1; o < 256; o <<= 1) {
        int a = (t >= o) ? sh[t - o] : 0;
        __syncthreads();
        sh[t] += a;
        __syncthreads();
    }
    if (t < SCAN_NB) g_bsum[t] = sh[t] - v;     // exclusive block offsets
    if (t == 0) g_rowptr[N_NODES] = N_EDGES;
}

__global__ void k_scan3() {
    int i = blockIdx.x * SCAN_BLK + threadIdx.x;
    if (i < N_NODES) g_rowptr[i] += g_bsum[blockIdx.x];
}

__global__ void k_scatter(const int* __restrict__ src, const int* __restrict__ dst) {
    int e = blockIdx.x * blockDim.x + threadIdx.x;
    if (e < N_EDGES) {
        int d = dst[e];
        int p = atomicAdd(&g_cursor[d], 1);
        g_col[g_rowptr[d] + p] = src[e];
    }
}

// ---------------- weight pre-transpose: Wt[k][c] = k<H ? Wl[c][k] : Wr[c][k-H]
__global__ void k_wt(const float* __restrict__ Wl1, const float* __restrict__ Wr1,
                     const float* __restrict__ Wl2, const float* __restrict__ Wr2,
                     const float* __restrict__ Wl3, const float* __restrict__ Wr3) {
    int idx = blockIdx.x * blockDim.x + threadIdx.x;
    if (idx >= 3 * 256 * H) return;
    int l = idx / (256 * H);
    int r = idx % (256 * H);
    int k = r / H, c = r % H;
    const float* Wl = (l == 0) ? Wl1 : (l == 1) ? Wl2 : Wl3;
    const float* Wr = (l == 0) ? Wr1 : (l == 1) ? Wr2 : Wr3;
    g_Wt[idx] = (k < H) ? Wl[c * H + k] : Wr[c * H + (k - H)];
}

// ---------------- node embedder: relu(LN(x @ W0^T + b0)) --------------------
__global__ void k_embed(const float* __restrict__ x, const float* __restrict__ W0,
                        const float* __restrict__ b0, const float* __restrict__ g0,
                        const float* __restrict__ be0) {
    int gw = (blockIdx.x * blockDim.x + threadIdx.x) >> 5;
    int lane = threadIdx.x & 31;
    if (gw >= N_NODES) return;
    float xd = (lane < DINP) ? x[gw * DINP + lane] : 0.f;
    float xs[DINP];
#pragma unroll
    for (int d = 0; d < DINP; d++) xs[d] = __shfl_sync(0xffffffffu, xd, d);
    float o[4];
#pragma unroll
    for (int j = 0; j < 4; j++) {
        int c = lane * 4 + j;
        float acc = b0[c];
#pragma unroll
        for (int d = 0; d < DINP; d++) acc = fmaf(xs[d], W0[c * DINP + d], acc);
        o[j] = acc;
    }
    float s1 = o[0] + o[1] + o[2] + o[3];
    float s2 = o[0]*o[0] + o[1]*o[1] + o[2]*o[2] + o[3]*o[3];
#pragma unroll
    for (int off = 16; off; off >>= 1) {
        s1 += __shfl_xor_sync(0xffffffffu, s1, off);
        s2 += __shfl_xor_sync(0xffffffffu, s2, off);
    }
    float m  = s1 * (1.f / H);
    float var = fmaxf(s2 * (1.f / H) - m * m, 0.f);
    float rs = rsqrtf(var + EPS);
    float4 out;
    float* po = &out.x;
#pragma unroll
    for (int j = 0; j < 4; j++) {
        int c = lane * 4 + j;
        po[j] = fmaxf((o[j] - m) * rs * g0[c] + be0[c], 0.f);
    }
    *(float4*)&g_hA[(size_t)gw * H + lane * 4] = out;
}

// ---------------- fused: gather-mean + dual-GEMM + LayerNorm + ReLU ---------
// Per block: 64 nodes.
// Phase 1: gather-mean neighbors into transposed smem AggT[128 k][64 nodes].
// Phase 2: out[n] = relu(LN( [agg_n ; h_n] (1x256) @ Wt (256x128) + bl ))
// Static smem < 48KB -> no cudaFuncSetAttribute needed.
#define AGT_PAD 66   // even pad: conflict-free column writes tolerable, aligned LDS64 reads
#define WS_PAD  132
#define HS_PAD  66

__global__ void __launch_bounds__(256) k_layer(
    const float* __restrict__ h, const float* __restrict__ Wt,
    const float* __restrict__ bl, const float* __restrict__ gg,
    const float* __restrict__ be, float* __restrict__ out)
{
    __shared__ __align__(16) float AggT[128 * AGT_PAD];  // 33792 B
    __shared__ __align__(16) float Ws[16 * WS_PAD];      //  8448 B
    __shared__ __align__(16) float Hs[16 * HS_PAD];      //  4224 B

    int t  = threadIdx.x;
    int tx = t & 31;      // lane
    int ty = t >> 5;      // warp id
    int nodeBase = blockIdx.x * 64;

    // ---- phase 1: gather-mean (warp ty handles nodes ty*8 .. ty*8+7) ----
#pragma unroll 1
    for (int i = 0; i < 8; i++) {
        int node = ty * 8 + i;
        int ng = nodeBase + node;
        float4 acc = make_float4(0.f, 0.f, 0.f, 0.f);
        if (ng < N_NODES) {
            int s = g_rowptr[ng], e = g_rowptr[ng + 1];
#pragma unroll 4
            for (int p = s; p < e; p++) {
                int sn = __ldg(&g_col[p]);
                float4 v = *(const float4*)(h + (size_t)sn * H + tx * 4);
                acc.x += v.x; acc.y += v.y; acc.z += v.z; acc.w += v.w;
            }
            float inv = 1.f / fmaxf((float)(e - s), 1.f);
            acc.x *= inv; acc.y *= inv; acc.z *= inv; acc.w *= inv;
        }
        AggT[(tx * 4 + 0) * AGT_PAD + node] = acc.x;
        AggT[(tx * 4 + 1) * AGT_PAD + node] = acc.y;
        AggT[(tx * 4 + 2) * AGT_PAD + node] = acc.z;
        AggT[(tx * 4 + 3) * AGT_PAD + node] = acc.w;
    }
    __syncthreads();

    // ---- phase 2: GEMM over K=256 ([agg ; h]) ----
    ull acc[4][4];   // [node-pair][channel] packed f32x2
#pragma unroll
    for (int p = 0; p < 4; p++)
#pragma unroll
        for (int j = 0; j < 4; j++) acc[p][j] = 0ull;

    // -- first half: K 0..127 from AggT (already in smem, no staging) --
#pragma unroll 1
    for (int kk = 0; kk < 128; kk += 16) {
#pragma unroll
        for (int it = 0; it < 8; it++) {
            int id = it * 256 + t;
            int k = id >> 7, c = id & 127;
            Ws[k * WS_PAD + c] = Wt[(kk + k) * H + c];
        }
        __syncthreads();
#pragma unroll
        for (int k = 0; k < 16; k++) {
            float4 w = *(const float4*)&Ws[k * WS_PAD + tx * 4];
            ull w0 = pack2(w.x), w1 = pack2(w.y), w2 = pack2(w.z), w3 = pack2(w.w);
#pragma unroll
            for (int p = 0; p < 4; p++) {
                ull a2 = *(const ull*)&AggT[(kk + k) * AGT_PAD + ty * 8 + p * 2];
                FMA2(acc[p][0], a2, w0);
                FMA2(acc[p][1], a2, w1);
                FMA2(acc[p][2], a2, w2);
                FMA2(acc[p][3], a2, w3);
            }
        }
        __syncthreads();
    }

    // -- second half: K 128..255 from h (staged 16-k slabs) --
    const int lk = t & 15;    // k within slab
    const int ln = t >> 4;    // node 0..15
#pragma unroll 1
    for (int kk = 0; kk < 128; kk += 16) {
#pragma unroll
        for (int it = 0; it < 4; it++) {
            int node = ln + it * 16;
            int ng = nodeBase + node;
            Hs[lk * HS_PAD + node] = (ng < N_NODES) ? h[(size_t)ng * H + kk + lk] : 0.f;
        }
#pragma unroll
        for (int it = 0; it < 8; it++) {
            int id = it * 256 + t;
            int k = id >> 7, c = id & 127;
            Ws[k * WS_PAD + c] = Wt[(128 + kk + k) * H + c];
        }
        __syncthreads();
#pragma unroll
        for (int k = 0; k < 16; k++) {
            float4 w = *(const float4*)&Ws[k * WS_PAD + tx * 4];
            ull w0 = pack2(w.x), w1 = pack2(w.y), w2 = pack2(w.z), w3 = pack2(w.w);
#pragma unroll
            for (int p = 0; p < 4; p++) {
                ull a2 = *(const ull*)&Hs[k * HS_PAD + ty * 8 + p * 2];
                FMA2(acc[p][0], a2, w0);
                FMA2(acc[p][1], a2, w1);
                FMA2(acc[p][2], a2, w2);
                FMA2(acc[p][3], a2, w3);
            }
        }
        __syncthreads();
    }

    // ---- epilogue: LayerNorm + ReLU ----
    float4 blv = *(const float4*)&bl[tx * 4];
    float4 gv  = *(const float4*)&gg[tx * 4];
    float4 bev = *(const float4*)&be[tx * 4];

#pragma unroll
    for (int p = 0; p < 4; p++) {
#pragma unroll
        for (int half = 0; half < 2; half++) {
            float v0 = (half ? f2hi(acc[p][0]) : f2lo(acc[p][0])) + blv.x;
            float v1 = (half ? f2hi(acc[p][1]) : f2lo(acc[p][1])) + blv.y;
            float v2 = (half ? f2hi(acc[p][2]) : f2lo(acc[p][2])) + blv.z;
            float v3 = (half ? f2hi(acc[p][3]) : f2lo(acc[p][3])) + blv.w;
            float s1 = v0 + v1 + v2 + v3;
            float s2 = v0*v0 + v1*v1 + v2*v2 + v3*v3;
#pragma unroll
            for (int off = 16; off; off >>= 1) {
                s1 += __shfl_xor_sync(0xffffffffu, s1, off);
                s2 += __shfl_xor_sync(0xffffffffu, s2, off);
            }
            float m   = s1 * (1.f / H);
            float var = fmaxf(s2 * (1.f / H) - m * m, 0.f);
            float rs  = rsqrtf(var + EPS);
            int ng = nodeBase + ty * 8 + p * 2 + half;
            if (ng < N_NODES) {
                float4 o;
                o.x = fmaxf((v0 - m) * rs * gv.x + bev.x, 0.f);
                o.y = fmaxf((v1 - m) * rs * gv.y + bev.y, 0.f);
                o.z = fmaxf((v2 - m) * rs * gv.z + bev.z, 0.f);
                o.w = fmaxf((v3 - m) * rs * gv.w + bev.w, 0.f);
                *(float4*)&out[(size_t)ng * H + tx * 4] = o;
            }
        }
    }
}

// ---------------- pooling ---------------------------------------------------
__global__ void k_startk(const int* __restrict__ batch) {
    int i = blockIdx.x * blockDim.x + threadIdx.x;
    if (i >= N_NODES) return;
    int b  = batch[i];
    int bp = (i == 0) ? -1 : batch[i - 1];
    for (int g = bp + 1; g <= b; g++) g_start[g] = i;
    if (i == N_NODES - 1)
        for (int g = b + 1; g <= BGRAPH; g++) g_start[g] = N_NODES;
}

__global__ void k_poolA(const float* __restrict__ ne) {
    int b  = blockIdx.x / POOL_CH;
    int ch = blockIdx.x % POOL_CH;
    int c  = threadIdx.x;
    int s = g_start[b], e = g_start[b + 1];
    int len = e - s;
    int cs = s + (int)(((long long)len * ch) / POOL_CH);
    int ce = s + (int)(((long long)len * (ch + 1)) / POOL_CH);
    float sum = 0.f, mx = -FLT_MAX;
    for (int n = cs; n < ce; n++) {
        float v = ne[(size_t)n * H + c];
        sum += v;
        mx = fmaxf(mx, v);
    }
    size_t base = ((size_t)(b * POOL_CH + ch)) * 2 * H;
    g_pp[base + c]     = sum;
    g_pp[base + H + c] = mx;
}

__global__ void k_poolB(float* __restrict__ out) {
    int b = blockIdx.x;
    int c = threadIdx.x;
    int s = g_start[b], e = g_start[b + 1];
    float sum = 0.f, mx = -FLT_MAX;
#pragma unroll
    for (int ch = 0; ch < POOL_CH; ch++) {
        size_t base = ((size_t)(b * POOL_CH + ch)) * 2 * H;
        sum += g_pp[base + c];
        mx = fmaxf(mx, g_pp[base + H + c]);
    }
    float cnt = (float)(e - s);
    size_t gbase = (size_t)N_NODES * H + (size_t)b * 2 * H;
    out[gbase + c]     = sum / fmaxf(cnt, 1.f);
    out[gbase + H + c] = mx;
}

// ---------------- launch ----------------------------------------------------
extern "C" void kernel_launch(void* const* d_in, const int* in_sizes, int n_in,
                              void* d_out, int out_size) {
    const float* x     = (const float*)d_in[0];
    const int*   ei    = (const int*)  d_in[1];
    const int*   batch = (const int*)  d_in[2];
    const float* W0  = (const float*)d_in[3];
    const float* b0  = (const float*)d_in[4];
    const float* g0  = (const float*)d_in[5];
    const float* be0 = (const float*)d_in[6];
    const float* Wl1 = (const float*)d_in[7];
    const float* bl1 = (const float*)d_in[8];
    const float* Wr1 = (const float*)d_in[9];
    const float* g1  = (const float*)d_in[10];
    const float* be1 = (const float*)d_in[11];
    const float* Wl2 = (const float*)d_in[12];
    const float* bl2 = (const float*)d_in[13];
    const float* Wr2 = (const float*)d_in[14];
    const float* g2  = (const float*)d_in[15];
    const float* be2 = (const float*)d_in[16];
    const float* Wl3 = (const float*)d_in[17];
    const float* bl3 = (const float*)d_in[18];
    const float* Wr3 = (const float*)d_in[19];
    const float* g3  = (const float*)d_in[20];
    const float* be3 = (const float*)d_in[21];

    const int* src = ei;
    const int* dst = ei + N_EDGES;
    float* out = (float*)d_out;

    float *hA, *hB, *Wt;
    cudaGetSymbolAddress((void**)&hA, g_hA);
    cudaGetSymbolAddress((void**)&hB, g_hB);
    cudaGetSymbolAddress((void**)&Wt, g_Wt);

    const int nodeBlocks = (N_NODES + 255) / 256;
    const int edgeBlocks = (N_EDGES + 255) / 256;
    const int warpBlocks = (N_NODES + 7) / 8;          // 8 warps/block
    const int tileBlocks = (N_NODES + 63) / 64;

    // CSR build (every launch — caching is forbidden)
    k_zero<<<nodeBlocks, 256>>>();
    k_deg<<<edgeBlocks, 256>>>(dst);
    k_scan1<<<SCAN_NB, SCAN_BLK>>>();
    k_scan2<<<1, 256>>>();
    k_scan3<<<SCAN_NB, SCAN_BLK>>>();
    k_scatter<<<edgeBlocks, 256>>>(src, dst);

    k_wt<<<(3 * 256 * H + 255) / 256, 256>>>(Wl1, Wr1, Wl2, Wr2, Wl3, Wr3);

    k_embed<<<warpBlocks, 256>>>(x, W0, b0, g0, be0);
    k_startk<<<nodeBlocks, 256>>>(batch);

    // layer 1: hA -> hB
    k_layer<<<tileBlocks, 256>>>(hA, Wt + 0 * 256 * H, bl1, g1, be1, hB);
    // layer 2: hB -> hA
    k_layer<<<tileBlocks, 256>>>(hB, Wt + 1 * 256 * H, bl2, g2, be2, hA);
    // layer 3: hA -> out (node_embed region)
    k_layer<<<tileBlocks, 256>>>(hA, Wt + 2 * 256 * H, bl3, g3, be3, out);

    k_poolA<<<BGRAPH * POOL_CH, H>>>(out);
    k_poolB<<<BGRAPH, H>>>(out);
}

// round 5
// speedup vs baseline: 1.1262x; 1.1262x over previous
#include <cuda_runtime.h>
#include <cfloat>
#include <stdint.h>

#define N_NODES 100000
#define N_EDGES 1600000
#define BGRAPH  64
#define DINP    9
#define H       128
#define EPS     1e-5f

#define SCAN_BLK 512
#define SCAN_NB  196   // ceil(100000/512)
#define POOL_CH  16

typedef unsigned long long ull;

// ---------------- scratch (device globals; no allocation allowed) -----------
__device__ float g_hA[N_NODES * H];
__device__ float g_hB[N_NODES * H];
__device__ float g_agg[N_NODES * H];
__device__ float g_Wt[3 * 256 * H];     // per-layer [256][128] = [Wl;Wr] transposed
__device__ int   g_rowptr[N_NODES + 1];
__device__ int   g_col[N_EDGES];
__device__ int   g_deg[N_NODES];
__device__ int   g_cursor[N_NODES];
__device__ int   g_bsum[SCAN_NB];
__device__ int   g_start[BGRAPH + 1];
__device__ float g_pp[BGRAPH * POOL_CH * 2 * H];

// ---------------- f32x2 helpers (Blackwell packed fp32) ---------------------
__device__ __forceinline__ ull pack2(float v) {
    ull r;
    unsigned u = __float_as_uint(v);
    asm("mov.b64 %0, {%1, %2};" : "=l"(r) : "r"(u), "r"(u));
    return r;
}
#define FMA2(d, a, b) asm("fma.rn.f32x2 %0, %1, %2, %0;" : "+l"(d) : "l"(a), "l"(b))

__device__ __forceinline__ float f2lo(ull v) {
    return __uint_as_float((unsigned)(v & 0xffffffffull));
}
__device__ __forceinline__ float f2hi(ull v) {
    return __uint_as_float((unsigned)(v >> 32));
}

// ---------------- CSR build -------------------------------------------------
__global__ void k_zero() {
    int i = blockIdx.x * blockDim.x + threadIdx.x;
    if (i < N_NODES) { g_deg[i] = 0; g_cursor[i] = 0; }
}

__global__ void k_deg(const int* __restrict__ dst) {
    int e = blockIdx.x * blockDim.x + threadIdx.x;
    if (e < N_EDGES) atomicAdd(&g_deg[dst[e]], 1);
}

__global__ void k_scan1() {
    __shared__ int sh[SCAN_BLK];
    int t = threadIdx.x;
    int i = blockIdx.x * SCAN_BLK + t;
    int v = (i < N_NODES) ? g_deg[i] : 0;
    sh[t] = v; __syncthreads();
    for (int o = 1; o < SCAN_BLK; o <<= 1) {
        int a = (t >= o) ? sh[t - o] : 0;
        __syncthreads();
        sh[t] += a;
        __syncthreads();
    }
    if (i < N_NODES) g_rowptr[i] = sh[t] - v;   // local exclusive
    if (t == SCAN_BLK - 1) g_bsum[blockIdx.x] = sh[t];
}

__global__ void k_scan2() {
    __shared__ int sh[256];
    int t = threadIdx.x;
    int v = (t < SCAN_NB) ? g_bsum[t] : 0;
    sh[t] = v; __syncthreads();
    for (int o = 1; o < 256; o <<= 1) {
        int a = (t >= o) ? sh[t - o] : 0;
        __syncthreads();
        sh[t] += a;
        __syncthreads();
    }
    if (t < SCAN_NB) g_bsum[t] = sh[t] - v;     // exclusive block offsets
    if (t == 0) g_rowptr[N_NODES] = N_EDGES;
}

__global__ void k_scan3() {
    int i = blockIdx.x * SCAN_BLK + threadIdx.x;
    if (i < N_NODES) g_rowptr[i] += g_bsum[blockIdx.x];
}

__global__ void k_scatter(const int* __restrict__ src, const int* __restrict__ dst) {
    int e = blockIdx.x * blockDim.x + threadIdx.x;
    if (e < N_EDGES) {
        int d = dst[e];
        int p = atomicAdd(&g_cursor[d], 1);
        g_col[g_rowptr[d] + p] = src[e];
    }
}

// ---------------- weight pre-transpose: Wt[k][c] = k<H ? Wl[c][k] : Wr[c][k-H]
__global__ void k_wt(const float* __restrict__ Wl1, const float* __restrict__ Wr1,
                     const float* __restrict__ Wl2, const float* __restrict__ Wr2,
                     const float* __restrict__ Wl3, const float* __restrict__ Wr3) {
    int idx = blockIdx.x * blockDim.x + threadIdx.x;
    if (idx >= 3 * 256 * H) return;
    int l = idx / (256 * H);
    int r = idx % (256 * H);
    int k = r / H, c = r % H;
    const float* Wl = (l == 0) ? Wl1 : (l == 1) ? Wl2 : Wl3;
    const float* Wr = (l == 0) ? Wr1 : (l == 1) ? Wr2 : Wr3;
    g_Wt[idx] = (k < H) ? Wl[c * H + k] : Wr[c * H + (k - H)];
}

// ---------------- node embedder: relu(LN(x @ W0^T + b0)) --------------------
__global__ void k_embed(const float* __restrict__ x, const float* __restrict__ W0,
                        const float* __restrict__ b0, const float* __restrict__ g0,
                        const float* __restrict__ be0) {
    int gw = (blockIdx.x * blockDim.x + threadIdx.x) >> 5;
    int lane = threadIdx.x & 31;
    if (gw >= N_NODES) return;
    float xd = (lane < DINP) ? x[gw * DINP + lane] : 0.f;
    float xs[DINP];
#pragma unroll
    for (int d = 0; d < DINP; d++) xs[d] = __shfl_sync(0xffffffffu, xd, d);
    float o[4];
#pragma unroll
    for (int j = 0; j < 4; j++) {
        int c = lane * 4 + j;
        float acc = b0[c];
#pragma unroll
        for (int d = 0; d < DINP; d++) acc = fmaf(xs[d], W0[c * DINP + d], acc);
        o[j] = acc;
    }
    float s1 = o[0] + o[1] + o[2] + o[3];
    float s2 = o[0]*o[0] + o[1]*o[1] + o[2]*o[2] + o[3]*o[3];
#pragma unroll
    for (int off = 16; off; off >>= 1) {
        s1 += __shfl_xor_sync(0xffffffffu, s1, off);
        s2 += __shfl_xor_sync(0xffffffffu, s2, off);
    }
    float m  = s1 * (1.f / H);
    float var = fmaxf(s2 * (1.f / H) - m * m, 0.f);
    float rs = rsqrtf(var + EPS);
    float4 out;
    float* po = &out.x;
#pragma unroll
    for (int j = 0; j < 4; j++) {
        int c = lane * 4 + j;
        po[j] = fmaxf((o[j] - m) * rs * g0[c] + be0[c], 0.f);
    }
    *(float4*)&g_hA[(size_t)gw * H + lane * 4] = out;
}

// ---------------- mean aggregation over CSR: warp per destination node ------
// High occupancy (no smem, few regs) hides L2 gather latency. Two independent
// accumulator sets (even/odd edges) raise MLP.
__global__ void k_agg(const float* __restrict__ h) {
    int gw = (blockIdx.x * blockDim.x + threadIdx.x) >> 5;
    int lane = threadIdx.x & 31;
    if (gw >= N_NODES) return;
    int s = g_rowptr[gw], e = g_rowptr[gw + 1];
    float4 a0 = make_float4(0.f, 0.f, 0.f, 0.f);
    float4 a1 = make_float4(0.f, 0.f, 0.f, 0.f);
    int p = s;
#pragma unroll 2
    for (; p + 1 < e; p += 2) {
        int sn0 = __ldg(&g_col[p]);
        int sn1 = __ldg(&g_col[p + 1]);
        float4 v0 = *(const float4*)(h + (size_t)sn0 * H + lane * 4);
        float4 v1 = *(const float4*)(h + (size_t)sn1 * H + lane * 4);
        a0.x += v0.x; a0.y += v0.y; a0.z += v0.z; a0.w += v0.w;
        a1.x += v1.x; a1.y += v1.y; a1.z += v1.z; a1.w += v1.w;
    }
    if (p < e) {
        int sn = __ldg(&g_col[p]);
        float4 v = *(const float4*)(h + (size_t)sn * H + lane * 4);
        a0.x += v.x; a0.y += v.y; a0.z += v.z; a0.w += v.w;
    }
    float inv = 1.f / fmaxf((float)(e - s), 1.f);
    float4 acc;
    acc.x = (a0.x + a1.x) * inv;
    acc.y = (a0.y + a1.y) * inv;
    acc.z = (a0.z + a1.z) * inv;
    acc.w = (a0.w + a1.w) * inv;
    *(float4*)(g_agg + (size_t)gw * H + lane * 4) = acc;
}

// ---------------- fused dual-GEMM + LayerNorm + ReLU ------------------------
// out[n] = relu(LN( [agg_n ; h_n] (1x256) @ Wt (256x128) + bl ))
// Tile: 64 nodes x 128 channels per block, K streamed in chunks of 32.
__global__ void __launch_bounds__(256, 2) k_layer(
    const float* __restrict__ h, const float* __restrict__ Wt,
    const float* __restrict__ bl, const float* __restrict__ gg,
    const float* __restrict__ be, float* __restrict__ out)
{
    __shared__ __align__(16) float As[32][66];    // [k][node]
    __shared__ __align__(16) float Ws[32][132];   // [k][chan]
    int t  = threadIdx.x;
    int tx = t & 31;      // channel group lane
    int ty = t >> 5;      // node-octet (== warp id)
    int nodeBase = blockIdx.x * 64;

    ull acc[4][4];   // [node-pair][channel] packed f32x2
#pragma unroll
    for (int p = 0; p < 4; p++)
#pragma unroll
        for (int j = 0; j < 4; j++) acc[p][j] = 0ull;

    const int lk = t & 31;   // k within tile for A-loads
    const int ln = t >> 5;   // node sub-index for A-loads

    for (int kk = 0; kk < 256; kk += 32) {
        const float* Asrc = (kk < H) ? g_agg : h;
        int ccol = kk + lk - ((kk < H) ? 0 : H);
#pragma unroll
        for (int it = 0; it < 8; it++) {
            int node = it * 8 + ln;
            int ng = nodeBase + node;
            As[lk][node] = (ng < N_NODES) ? Asrc[(size_t)ng * H + ccol] : 0.f;
        }
#pragma unroll
        for (int it = 0; it < 16; it++) {
            int id = it * 256 + t;
            int k = id >> 7, c = id & 127;
            Ws[k][c] = Wt[(kk + k) * H + c];
        }
        __syncthreads();
#pragma unroll
        for (int k = 0; k < 32; k++) {
            float4 w = *(const float4*)&Ws[k][tx * 4];
            ull w0 = pack2(w.x), w1 = pack2(w.y), w2 = pack2(w.z), w3 = pack2(w.w);
#pragma unroll
            for (int p = 0; p < 4; p++) {
                ull a2 = *(const ull*)&As[k][ty * 8 + p * 2];
                FMA2(acc[p][0], a2, w0);
                FMA2(acc[p][1], a2, w1);
                FMA2(acc[p][2], a2, w2);
                FMA2(acc[p][3], a2, w3);
            }
        }
        __syncthreads();
    }

    float4 blv = *(const float4*)&bl[tx * 4];
    float4 gv  = *(const float4*)&gg[tx * 4];
    float4 bev = *(const float4*)&be[tx * 4];

#pragma unroll
    for (int p = 0; p < 4; p++) {
#pragma unroll
        for (int half = 0; half < 2; half++) {
            float v0 = (half ? f2hi(acc[p][0]) : f2lo(acc[p][0])) + blv.x;
            float v1 = (half ? f2hi(acc[p][1]) : f2lo(acc[p][1])) + blv.y;
            float v2 = (half ? f2hi(acc[p][2]) : f2lo(acc[p][2])) + blv.z;
            float v3 = (half ? f2hi(acc[p][3]) : f2lo(acc[p][3])) + blv.w;
            float s1 = v0 + v1 + v2 + v3;
            float s2 = v0*v0 + v1*v1 + v2*v2 + v3*v3;
#pragma unroll
            for (int off = 16; off; off >>= 1) {
                s1 += __shfl_xor_sync(0xffffffffu, s1, off);
                s2 += __shfl_xor_sync(0xffffffffu, s2, off);
            }
            float m   = s1 * (1.f / H);
            float var = fmaxf(s2 * (1.f / H) - m * m, 0.f);
            float rs  = rsqrtf(var + EPS);
            int ng = nodeBase + ty * 8 + p * 2 + half;
            if (ng < N_NODES) {
                float4 o;
                o.x = fmaxf((v0 - m) * rs * gv.x + bev.x, 0.f);
                o.y = fmaxf((v1 - m) * rs * gv.y + bev.y, 0.f);
                o.z = fmaxf((v2 - m) * rs * gv.z + bev.z, 0.f);
                o.w = fmaxf((v3 - m) * rs * gv.w + bev.w, 0.f);
                *(float4*)&out[(size_t)ng * H + tx * 4] = o;
            }
        }
    }
}

// ---------------- pooling (two-stage) ---------------------------------------
__global__ void k_startk(const int* __restrict__ batch) {
    int i = blockIdx.x * blockDim.x + threadIdx.x;
    if (i >= N_NODES) return;
    int b  = batch[i];
    int bp = (i == 0) ? -1 : batch[i - 1];
    for (int g = bp + 1; g <= b; g++) g_start[g] = i;
    if (i == N_NODES - 1)
        for (int g = b + 1; g <= BGRAPH; g++) g_start[g] = N_NODES;
}

__global__ void k_poolA(const float* __restrict__ ne) {
    int b  = blockIdx.x / POOL_CH;
    int ch = blockIdx.x % POOL_CH;
    int c  = threadIdx.x;
    int s = g_start[b], e = g_start[b + 1];
    int len = e - s;
    int cs = s + (int)(((long long)len * ch) / POOL_CH);
    int ce = s + (int)(((long long)len * (ch + 1)) / POOL_CH);
    float sum = 0.f, mx = -FLT_MAX;
    for (int n = cs; n < ce; n++) {
        float v = ne[(size_t)n * H + c];
        sum += v;
        mx = fmaxf(mx, v);
    }
    size_t base = ((size_t)(b * POOL_CH + ch)) * 2 * H;
    g_pp[base + c]     = sum;
    g_pp[base + H + c] = mx;
}

__global__ void k_poolB(float* __restrict__ out) {
    int b = blockIdx.x;
    int c = threadIdx.x;
    int s = g_start[b], e = g_start[b + 1];
    float sum = 0.f, mx = -FLT_MAX;
#pragma unroll
    for (int ch = 0; ch < POOL_CH; ch++) {
        size_t base = ((size_t)(b * POOL_CH + ch)) * 2 * H;
        sum += g_pp[base + c];
        mx = fmaxf(mx, g_pp[base + H + c]);
    }
    float cnt = (float)(e - s);
    size_t gbase = (size_t)N_NODES * H + (size_t)b * 2 * H;
    out[gbase + c]     = sum / fmaxf(cnt, 1.f);
    out[gbase + H + c] = mx;
}

// ---------------- launch ----------------------------------------------------
extern "C" void kernel_launch(void* const* d_in, const int* in_sizes, int n_in,
                              void* d_out, int out_size) {
    const float* x     = (const float*)d_in[0];
    const int*   ei    = (const int*)  d_in[1];
    const int*   batch = (const int*)  d_in[2];
    const float* W0  = (const float*)d_in[3];
    const float* b0  = (const float*)d_in[4];
    const float* g0  = (const float*)d_in[5];
    const float* be0 = (const float*)d_in[6];
    const float* Wl1 = (const float*)d_in[7];
    const float* bl1 = (const float*)d_in[8];
    const float* Wr1 = (const float*)d_in[9];
    const float* g1  = (const float*)d_in[10];
    const float* be1 = (const float*)d_in[11];
    const float* Wl2 = (const float*)d_in[12];
    const float* bl2 = (const float*)d_in[13];
    const float* Wr2 = (const float*)d_in[14];
    const float* g2  = (const float*)d_in[15];
    const float* be2 = (const float*)d_in[16];
    const float* Wl3 = (const float*)d_in[17];
    const float* bl3 = (const float*)d_in[18];
    const float* Wr3 = (const float*)d_in[19];
    const float* g3  = (const float*)d_in[20];
    const float* be3 = (const float*)d_in[21];

    const int* src = ei;
    const int* dst = ei + N_EDGES;
    float* out = (float*)d_out;

    float *hA, *hB, *Wt;
    cudaGetSymbolAddress((void**)&hA, g_hA);
    cudaGetSymbolAddress((void**)&hB, g_hB);
    cudaGetSymbolAddress((void**)&Wt, g_Wt);

    const int nodeBlocks = (N_NODES + 255) / 256;
    const int edgeBlocks = (N_EDGES + 255) / 256;
    const int warpBlocks = (N_NODES + 7) / 8;          // 8 warps/block
    const int tileBlocks = (N_NODES + 63) / 64;

    // CSR build (every launch — caching is forbidden)
    k_zero<<<nodeBlocks, 256>>>();
    k_deg<<<edgeBlocks, 256>>>(dst);
    k_scan1<<<SCAN_NB, SCAN_BLK>>>();
    k_scan2<<<1, 256>>>();
    k_scan3<<<SCAN_NB, SCAN_BLK>>>();
    k_scatter<<<edgeBlocks, 256>>>(src, dst);

    k_wt<<<(3 * 256 * H + 255) / 256, 256>>>(Wl1, Wr1, Wl2, Wr2, Wl3, Wr3);

    k_embed<<<warpBlocks, 256>>>(x, W0, b0, g0, be0);
    k_startk<<<nodeBlocks, 256>>>(batch);

    // layer 1: hA -> hB
    k_agg<<<warpBlocks, 256>>>(hA);
    k_layer<<<tileBlocks, 256>>>(hA, Wt + 0 * 256 * H, bl1, g1, be1, hB);
    // layer 2: hB -> hA
    k_agg<<<warpBlocks, 256>>>(hB);
    k_layer<<<tileBlocks, 256>>>(hB, Wt + 1 * 256 * H, bl2, g2, be2, hA);
    // layer 3: hA -> out (node_embed region)
    k_agg<<<warpBlocks, 256>>>(hA);
    k_layer<<<tileBlocks, 256>>>(hA, Wt + 2 * 256 * H, bl3, g3, be3, out);

    k_poolA<<<BGRAPH * POOL_CH, H>>>(out);
    k_poolB<<<BGRAPH, H>>>(out);
}

// round 6
// speedup vs baseline: 1.2391x; 1.1002x over previous
#include <cuda_runtime.h>
#include <cfloat>
#include <stdint.h>

#define N_NODES 100000
#define N_EDGES 1600000
#define BGRAPH  64
#define DINP    9
#define H       128
#define EPS     1e-5f

#define SCAN_BLK 512
#define SCAN_NB  196   // ceil(100000/512)
#define POOL_CH  16

typedef unsigned u32;

// ---------------- scratch (device globals; no allocation allowed) -----------
// bf16 feature storage: packed pairs (channel c even in low 16 bits), hi/lo split.
__device__ u32 g_hAHi[N_NODES * 64];
__device__ u32 g_hALo[N_NODES * 64];
__device__ u32 g_hBHi[N_NODES * 64];
__device__ u32 g_hBLo[N_NODES * 64];
__device__ u32 g_agHi[N_NODES * 64];
__device__ u32 g_agLo[N_NODES * 64];
__device__ u32 g_WHi[3 * 128 * 128];   // per layer: [c 128][k 256] bf16 pairs
__device__ u32 g_WLo[3 * 128 * 128];
__device__ int g_rowptr[N_NODES + 1];
__device__ int g_col[N_EDGES];
__device__ int g_deg[N_NODES];
__device__ int g_cursor[N_NODES];
__device__ int g_bsum[SCAN_NB];
__device__ int g_start[BGRAPH + 1];
__device__ float g_pp[BGRAPH * POOL_CH * 2 * H];

// ---------------- bf16 helpers ----------------------------------------------
__device__ __forceinline__ u32 bf16rn(float f) {
    u32 u = __float_as_uint(f);
    return (u + 0x7fffu + ((u >> 16) & 1u)) >> 16;
}
__device__ __forceinline__ float bfToF(u32 hi16shifted) {   // pass (bits<<16)
    return __uint_as_float(hi16shifted);
}
// split f into bf16 hi/lo bits
__device__ __forceinline__ void bfsplit(float f, u32& hi, u32& lo) {
    hi = bf16rn(f);
    float r = f - __uint_as_float(hi << 16);
    lo = bf16rn(r);
}

#define MMA_BF16(c0,c1,c2,c3,a0,a1,a2,a3,b0,b1) \
    asm volatile("mma.sync.aligned.m16n8k16.row.col.f32.bf16.bf16.f32 " \
        "{%0,%1,%2,%3}, {%4,%5,%6,%7}, {%8,%9}, {%0,%1,%2,%3};\n" \
        : "+f"(c0), "+f"(c1), "+f"(c2), "+f"(c3) \
        : "r"(a0), "r"(a1), "r"(a2), "r"(a3), "r"(b0), "r"(b1))

// ---------------- CSR build -------------------------------------------------
__global__ void k_zero() {
    int i = blockIdx.x * blockDim.x + threadIdx.x;
    if (i < N_NODES) { g_deg[i] = 0; g_cursor[i] = 0; }
}

__global__ void k_deg(const int* __restrict__ dst) {
    int e = blockIdx.x * blockDim.x + threadIdx.x;
    if (e < N_EDGES) atomicAdd(&g_deg[dst[e]], 1);
}

__global__ void k_scan1() {
    __shared__ int sh[SCAN_BLK];
    int t = threadIdx.x;
    int i = blockIdx.x * SCAN_BLK + t;
    int v = (i < N_NODES) ? g_deg[i] : 0;
    sh[t] = v; __syncthreads();
    for (int o = 1; o < SCAN_BLK; o <<= 1) {
        int a = (t >= o) ? sh[t - o] : 0;
        __syncthreads();
        sh[t] += a;
        __syncthreads();
    }
    if (i < N_NODES) g_rowptr[i] = sh[t] - v;
    if (t == SCAN_BLK - 1) g_bsum[blockIdx.x] = sh[t];
}

__global__ void k_scan2() {
    __shared__ int sh[256];
    int t = threadIdx.x;
    int v = (t < SCAN_NB) ? g_bsum[t] : 0;
    sh[t] = v; __syncthreads();
    for (int o = 1; o < 256; o <<= 1) {
        int a = (t >= o) ? sh[t - o] : 0;
        __syncthreads();
        sh[t] += a;
        __syncthreads();
    }
    if (t < SCAN_NB) g_bsum[t] = sh[t] - v;
    if (t == 0) g_rowptr[N_NODES] = N_EDGES;
}

__global__ void k_scan3() {
    int i = blockIdx.x * SCAN_BLK + threadIdx.x;
    if (i < N_NODES) g_rowptr[i] += g_bsum[blockIdx.x];
}

__global__ void k_scatter(const int* __restrict__ src, const int* __restrict__ dst) {
    int e = blockIdx.x * blockDim.x + threadIdx.x;
    if (e < N_EDGES) {
        int d = dst[e];
        int p = atomicAdd(&g_cursor[d], 1);
        g_col[g_rowptr[d] + p] = src[e];
    }
}

// ---------------- weight split: W[c][k] = k<128 ? Wl[c][k] : Wr[c][k-128] ----
__global__ void k_wsplit(const float* __restrict__ Wl1, const float* __restrict__ Wr1,
                         const float* __restrict__ Wl2, const float* __restrict__ Wr2,
                         const float* __restrict__ Wl3, const float* __restrict__ Wr3) {
    int idx = blockIdx.x * blockDim.x + threadIdx.x;   // u32 index
    if (idx >= 3 * 128 * 128) return;
    int l = idx / (128 * 128);
    int r = idx % (128 * 128);
    int c = r >> 7;            // 0..127
    int kp = r & 127;          // k-pair
    int k0 = kp * 2;
    const float* Wl = (l == 0) ? Wl1 : (l == 1) ? Wl2 : Wl3;
    const float* Wr = (l == 0) ? Wr1 : (l == 1) ? Wr2 : Wr3;
    float w0 = (k0 < 128) ? Wl[c * 128 + k0] : Wr[c * 128 + k0 - 128];
    float w1 = (k0 + 1 < 128) ? Wl[c * 128 + k0 + 1] : Wr[c * 128 + k0 + 1 - 128];
    u32 h0, l0, h1, l1;
    bfsplit(w0, h0, l0);
    bfsplit(w1, h1, l1);
    g_WHi[idx] = h0 | (h1 << 16);
    g_WLo[idx] = l0 | (l1 << 16);
}

// ---------------- node embedder: relu(LN(x @ W0^T + b0)) -> bf16 hi/lo ------
__global__ void k_embed(const float* __restrict__ x, const float* __restrict__ W0,
                        const float* __restrict__ b0, const float* __restrict__ g0,
                        const float* __restrict__ be0) {
    int gw = (blockIdx.x * blockDim.x + threadIdx.x) >> 5;
    int lane = threadIdx.x & 31;
    if (gw >= N_NODES) return;
    float xd = (lane < DINP) ? x[gw * DINP + lane] : 0.f;
    float xs[DINP];
#pragma unroll
    for (int d = 0; d < DINP; d++) xs[d] = __shfl_sync(0xffffffffu, xd, d);
    float o[4];
#pragma unroll
    for (int j = 0; j < 4; j++) {
        int c = lane * 4 + j;
        float acc = b0[c];
#pragma unroll
        for (int d = 0; d < DINP; d++) acc = fmaf(xs[d], W0[c * DINP + d], acc);
        o[j] = acc;
    }
    float s1 = o[0] + o[1] + o[2] + o[3];
    float s2 = o[0]*o[0] + o[1]*o[1] + o[2]*o[2] + o[3]*o[3];
#pragma unroll
    for (int off = 16; off; off >>= 1) {
        s1 += __shfl_xor_sync(0xffffffffu, s1, off);
        s2 += __shfl_xor_sync(0xffffffffu, s2, off);
    }
    float m  = s1 * (1.f / H);
    float var = fmaxf(s2 * (1.f / H) - m * m, 0.f);
    float rs = rsqrtf(var + EPS);
    u32 hb[4], lb[4];
#pragma unroll
    for (int j = 0; j < 4; j++) {
        int c = lane * 4 + j;
        float v = fmaxf((o[j] - m) * rs * g0[c] + be0[c], 0.f);
        bfsplit(v, hb[j], lb[j]);
    }
    size_t base = (size_t)gw * 64 + lane * 2;
    *(uint2*)&g_hAHi[base] = make_uint2(hb[0] | (hb[1] << 16), hb[2] | (hb[3] << 16));
    *(uint2*)&g_hALo[base] = make_uint2(lb[0] | (lb[1] << 16), lb[2] | (lb[3] << 16));
}

// ---------------- mean aggregation over CSR: warp per destination node ------
__global__ void k_agg(const u32* __restrict__ hHi, const u32* __restrict__ hLo) {
    int gw = (blockIdx.x * blockDim.x + threadIdx.x) >> 5;
    int lane = threadIdx.x & 31;
    if (gw >= N_NODES) return;
    int s = g_rowptr[gw], e = g_rowptr[gw + 1];
    float a0 = 0.f, a1 = 0.f, a2 = 0.f, a3 = 0.f;
    for (int p = s; p < e; p++) {
        int sn = __ldg(&g_col[p]);
        size_t base = (size_t)sn * 64 + lane * 2;
        uint2 hw = *(const uint2*)&hHi[base];
        uint2 lw = *(const uint2*)&hLo[base];
        a0 += __uint_as_float(hw.x << 16) + __uint_as_float(lw.x << 16);
        a1 += __uint_as_float(hw.x & 0xffff0000u) + __uint_as_float(lw.x & 0xffff0000u);
        a2 += __uint_as_float(hw.y << 16) + __uint_as_float(lw.y << 16);
        a3 += __uint_as_float(hw.y & 0xffff0000u) + __uint_as_float(lw.y & 0xffff0000u);
    }
    float inv = 1.f / fmaxf((float)(e - s), 1.f);
    a0 *= inv; a1 *= inv; a2 *= inv; a3 *= inv;
    u32 h0, l0, h1, l1, h2, l2, h3, l3;
    bfsplit(a0, h0, l0); bfsplit(a1, h1, l1);
    bfsplit(a2, h2, l2); bfsplit(a3, h3, l3);
    size_t base = (size_t)gw * 64 + lane * 2;
    *(uint2*)&g_agHi[base] = make_uint2(h0 | (h1 << 16), h2 | (h3 << 16));
    *(uint2*)&g_agLo[base] = make_uint2(l0 | (l1 << 16), l2 | (l3 << 16));
}

// ---------------- tensor-core layer: bf16x3 MMA + LayerNorm + ReLU ----------
// Tile: 128 nodes x 128 channels. 8 warps; warp w owns rows w*16..w*16+15.
// K = 256 = [agg(128) ; h(128)], staged in 32-k chunks.
// Smem layout per chunk: rows of 16 u32 (32 bf16), k-permuted within each 16-k
// block for LDS.64 fragment loads, XOR-swizzled with bit ((row>>1)&1)<<3 for
// bank-conflict-free access.
__global__ void __launch_bounds__(256, 2) k_layer(
    const u32* __restrict__ agHi, const u32* __restrict__ agLo,
    const u32* __restrict__ hHi,  const u32* __restrict__ hLo,
    const u32* __restrict__ WHi,  const u32* __restrict__ WLo,
    const float* __restrict__ bl, const float* __restrict__ gg,
    const float* __restrict__ be,
    float* __restrict__ outF, u32* __restrict__ outHi, u32* __restrict__ outLo)
{
    __shared__ __align__(16) u32 AsHi[128 * 16];
    __shared__ __align__(16) u32 AsLo[128 * 16];
    __shared__ __align__(16) u32 WsHi[128 * 16];
    __shared__ __align__(16) u32 WsLo[128 * 16];
    __shared__ float sBl[128], sGg[128], sBe[128];

    int t = threadIdx.x;
    int lane = t & 31;
    int wid = t >> 5;
    int g  = lane >> 2;     // 0..7
    int t2 = lane & 3;      // 0..3
    int m0 = wid * 16;
    int nodeBase = blockIdx.x * 128;

    if (t < 128) { sBl[t] = bl[t]; sGg[t] = gg[t]; sBe[t] = be[t]; }

    float acc[16][4];
#pragma unroll
    for (int nt = 0; nt < 16; nt++)
#pragma unroll
        for (int j = 0; j < 4; j++) acc[nt][j] = 0.f;

#pragma unroll 1
    for (int kk = 0; kk < 256; kk += 32) {
        // ---- stage A (features) and W chunk ----
        const u32* sHi; const u32* sLo; int koff;
        if (kk < 128) { sHi = agHi; sLo = agLo; koff = kk; }
        else          { sHi = hHi;  sLo = hLo;  koff = kk - 128; }
#pragma unroll
        for (int it = 0; it < 8; it++) {
            int i = it * 256 + t;           // 0..2047
            int row = i >> 4;
            int j32 = i & 15;
            int blk = j32 >> 3, j = j32 & 7;
            int pj = (j < 4) ? (2 * j) : (2 * j - 7);
            int sIdx = (row * 16 + blk * 8 + pj) ^ (((row >> 1) & 1) << 3);
            int gnode = nodeBase + row;
            u32 vHi = 0, vLo = 0;
            if (gnode < N_NODES) {
                size_t gidx = (size_t)gnode * 64 + (koff >> 1) + blk * 8 + j;
                vHi = sHi[gidx]; vLo = sLo[gidx];
            }
            AsHi[sIdx] = vHi; AsLo[sIdx] = vLo;
            size_t widx = (size_t)row * 128 + (kk >> 1) + blk * 8 + j;
            WsHi[sIdx] = WHi[widx]; WsLo[sIdx] = WLo[widx];
        }
        __syncthreads();

        // ---- compute: 2 k16-blocks ----
#pragma unroll
        for (int blk = 0; blk < 2; blk++) {
            int rA = m0 + g, rB = m0 + g + 8;
            int iA = (rA * 16 + blk * 8 + 2 * t2) ^ (((rA >> 1) & 1) << 3);
            int iB = (rB * 16 + blk * 8 + 2 * t2) ^ (((rB >> 1) & 1) << 3);
            uint2 a02h = *(const uint2*)&AsHi[iA];
            uint2 a13h = *(const uint2*)&AsHi[iB];
            uint2 a02l = *(const uint2*)&AsLo[iA];
            uint2 a13l = *(const uint2*)&AsLo[iB];
#pragma unroll
            for (int nt = 0; nt < 16; nt++) {
                int c = nt * 8 + g;
                int iW = (c * 16 + blk * 8 + 2 * t2) ^ (((c >> 1) & 1) << 3);
                uint2 bh = *(const uint2*)&WsHi[iW];
                uint2 blo = *(const uint2*)&WsLo[iW];
                MMA_BF16(acc[nt][0], acc[nt][1], acc[nt][2], acc[nt][3],
                         a02h.x, a13h.x, a02h.y, a13h.y, bh.x, bh.y);
                MMA_BF16(acc[nt][0], acc[nt][1], acc[nt][2], acc[nt][3],
                         a02h.x, a13h.x, a02h.y, a13h.y, blo.x, blo.y);
                MMA_BF16(acc[nt][0], acc[nt][1], acc[nt][2], acc[nt][3],
                         a02l.x, a13l.x, a02l.y, a13l.y, bh.x, bh.y);
            }
        }
        __syncthreads();
    }

    // ---- epilogue: add bias, LayerNorm per row, ReLU, store ----
    // thread holds rows rA = m0+g (acc[nt][0..1]) and rB = m0+g+8 (acc[nt][2..3]),
    // cols nt*8 + 2*t2 + {0,1}. Full 128 cols of a row live in 4 lanes (same g).
    float sA1 = 0.f, sA2 = 0.f, sB1 = 0.f, sB2 = 0.f;
#pragma unroll
    for (int nt = 0; nt < 16; nt++) {
        int c0 = nt * 8 + 2 * t2;
        float b0 = sBl[c0], b1 = sBl[c0 + 1];
        float va0 = acc[nt][0] + b0, va1 = acc[nt][1] + b1;
        float vb0 = acc[nt][2] + b0, vb1 = acc[nt][3] + b1;
        sA1 += va0 + va1; sA2 += va0 * va0 + va1 * va1;
        sB1 += vb0 + vb1; sB2 += vb0 * vb0 + vb1 * vb1;
    }
#pragma unroll
    for (int off = 1; off <= 2; off <<= 1) {
        sA1 += __shfl_xor_sync(0xffffffffu, sA1, off);
        sA2 += __shfl_xor_sync(0xffffffffu, sA2, off);
        sB1 += __shfl_xor_sync(0xffffffffu, sB1, off);
        sB2 += __shfl_xor_sync(0xffffffffu, sB2, off);
    }
    float mA = sA1 * (1.f / H);
    float vA = fmaxf(sA2 * (1.f / H) - mA * mA, 0.f);
    float rsA = rsqrtf(vA + EPS);
    float mB = sB1 * (1.f / H);
    float vB = fmaxf(sB2 * (1.f / H) - mB * mB, 0.f);
    float rsB = rsqrtf(vB + EPS);

    int gA = nodeBase + m0 + g;
    int gB = gA + 8;
    bool wA = gA < N_NODES, wB = gB < N_NODES;

#pragma unroll
    for (int nt = 0; nt < 16; nt++) {
        int c0 = nt * 8 + 2 * t2;
        float b0 = sBl[c0], b1 = sBl[c0 + 1];
        float gg0 = sGg[c0], gg1 = sGg[c0 + 1];
        float be0 = sBe[c0], be1 = sBe[c0 + 1];
        float oa0 = fmaxf((acc[nt][0] + b0 - mA) * rsA * gg0 + be0, 0.f);
        float oa1 = fmaxf((acc[nt][1] + b1 - mA) * rsA * gg1 + be1, 0.f);
        float ob0 = fmaxf((acc[nt][2] + b0 - mB) * rsB * gg0 + be0, 0.f);
        float ob1 = fmaxf((acc[nt][3] + b1 - mB) * rsB * gg1 + be1, 0.f);
        if (outF) {
            if (wA) *(float2*)&outF[(size_t)gA * 128 + c0] = make_float2(oa0, oa1);
            if (wB) *(float2*)&outF[(size_t)gB * 128 + c0] = make_float2(ob0, ob1);
        } else {
            u32 h0, l0, h1, l1;
            if (wA) {
                bfsplit(oa0, h0, l0); bfsplit(oa1, h1, l1);
                size_t ia = (size_t)gA * 64 + (c0 >> 1);
                outHi[ia] = h0 | (h1 << 16);
                outLo[ia] = l0 | (l1 << 16);
            }
            if (wB) {
                bfsplit(ob0, h0, l0); bfsplit(ob1, h1, l1);
                size_t ib = (size_t)gB * 64 + (c0 >> 1);
                outHi[ib] = h0 | (h1 << 16);
                outLo[ib] = l0 | (l1 << 16);
            }
        }
    }
}

// ---------------- pooling (two-stage) ---------------------------------------
__global__ void k_startk(const int* __restrict__ batch) {
    int i = blockIdx.x * blockDim.x + threadIdx.x;
    if (i >= N_NODES) return;
    int b  = batch[i];
    int bp = (i == 0) ? -1 : batch[i - 1];
    for (int g = bp + 1; g <= b; g++) g_start[g] = i;
    if (i == N_NODES - 1)
        for (int g = b + 1; g <= BGRAPH; g++) g_start[g] = N_NODES;
}

__global__ void k_poolA(const float* __restrict__ ne) {
    int b  = blockIdx.x / POOL_CH;
    int ch = blockIdx.x % POOL_CH;
    int c  = threadIdx.x;
    int s = g_start[b], e = g_start[b + 1];
    int len = e - s;
    int cs = s + (int)(((long long)len * ch) / POOL_CH);
    int ce = s + (int)(((long long)len * (ch + 1)) / POOL_CH);
    float sum = 0.f, mx = -FLT_MAX;
    for (int n = cs; n < ce; n++) {
        float v = ne[(size_t)n * H + c];
        sum += v;
        mx = fmaxf(mx, v);
    }
    size_t base = ((size_t)(b * POOL_CH + ch)) * 2 * H;
    g_pp[base + c]     = sum;
    g_pp[base + H + c] = mx;
}

__global__ void k_poolB(float* __restrict__ out) {
    int b = blockIdx.x;
    int c = threadIdx.x;
    int s = g_start[b], e = g_start[b + 1];
    float sum = 0.f, mx = -FLT_MAX;
#pragma unroll
    for (int ch = 0; ch < POOL_CH; ch++) {
        size_t base = ((size_t)(b * POOL_CH + ch)) * 2 * H;
        sum += g_pp[base + c];
        mx = fmaxf(mx, g_pp[base + H + c]);
    }
    float cnt = (float)(e - s);
    size_t gbase = (size_t)N_NODES * H + (size_t)b * 2 * H;
    out[gbase + c]     = sum / fmaxf(cnt, 1.f);
    out[gbase + H + c] = mx;
}

// ---------------- launch ----------------------------------------------------
extern "C" void kernel_launch(void* const* d_in, const int* in_sizes, int n_in,
                              void* d_out, int out_size) {
    const float* x     = (const float*)d_in[0];
    const int*   ei    = (const int*)  d_in[1];
    const int*   batch = (const int*)  d_in[2];
    const float* W0  = (const float*)d_in[3];
    const float* b0  = (const float*)d_in[4];
    const float* g0  = (const float*)d_in[5];
    const float* be0 = (const float*)d_in[6];
    const float* Wl1 = (const float*)d_in[7];
    const float* bl1 = (const float*)d_in[8];
    const float* Wr1 = (const float*)d_in[9];
    const float* g1  = (const float*)d_in[10];
    const float* be1 = (const float*)d_in[11];
    const float* Wl2 = (const float*)d_in[12];
    const float* bl2 = (const float*)d_in[13];
    const float* Wr2 = (const float*)d_in[14];
    const float* g2  = (const float*)d_in[15];
    const float* be2 = (const float*)d_in[16];
    const float* Wl3 = (const float*)d_in[17];
    const float* bl3 = (const float*)d_in[18];
    const float* Wr3 = (const float*)d_in[19];
    const float* g3  = (const float*)d_in[20];
    const float* be3 = (const float*)d_in[21];

    const int* src = ei;
    const int* dst = ei + N_EDGES;
    float* out = (float*)d_out;

    u32 *hAHi, *hALo, *hBHi, *hBLo, *agHi, *agLo, *WHi, *WLo;
    cudaGetSymbolAddress((void**)&hAHi, g_hAHi);
    cudaGetSymbolAddress((void**)&hALo, g_hALo);
    cudaGetSymbolAddress((void**)&hBHi, g_hBHi);
    cudaGetSymbolAddress((void**)&hBLo, g_hBLo);
    cudaGetSymbolAddress((void**)&agHi, g_agHi);
    cudaGetSymbolAddress((void**)&agLo, g_agLo);
    cudaGetSymbolAddress((void**)&WHi, g_WHi);
    cudaGetSymbolAddress((void**)&WLo, g_WLo);

    const int nodeBlocks = (N_NODES + 255) / 256;
    const int edgeBlocks = (N_EDGES + 255) / 256;
    const int warpBlocks = (N_NODES + 7) / 8;          // 8 warps/block
    const int tileBlocks = (N_NODES + 127) / 128;      // 782

    // CSR build (every launch — caching is forbidden)
    k_zero<<<nodeBlocks, 256>>>();
    k_deg<<<edgeBlocks, 256>>>(dst);
    k_scan1<<<SCAN_NB, SCAN_BLK>>>();
    k_scan2<<<1, 256>>>();
    k_scan3<<<SCAN_NB, SCAN_BLK>>>();
    k_scatter<<<edgeBlocks, 256>>>(src, dst);

    k_wsplit<<<(3 * 128 * 128 + 255) / 256, 256>>>(Wl1, Wr1, Wl2, Wr2, Wl3, Wr3);

    k_embed<<<warpBlocks, 256>>>(x, W0, b0, g0, be0);
    k_startk<<<nodeBlocks, 256>>>(batch);

    // layer 1: A -> B
    k_agg<<<warpBlocks, 256>>>(hAHi, hALo);
    k_layer<<<tileBlocks, 256>>>(agHi, agLo, hAHi, hALo,
                                 WHi + 0 * 128 * 128, WLo + 0 * 128 * 128,
                                 bl1, g1, be1, nullptr, hBHi, hBLo);
    // layer 2: B -> A
    k_agg<<<warpBlocks, 256>>>(hBHi, hBLo);
    k_layer<<<tileBlocks, 256>>>(agHi, agLo, hBHi, hBLo,
                                 WHi + 1 * 128 * 128, WLo + 1 * 128 * 128,
                                 bl2, g2, be2, nullptr, hAHi, hALo);
    // layer 3: A -> out (fp32 node_embed)
    k_agg<<<warpBlocks, 256>>>(hAHi, hALo);
    k_layer<<<tileBlocks, 256>>>(agHi, agLo, hAHi, hALo,
                                 WHi + 2 * 128 * 128, WLo + 2 * 128 * 128,
                                 bl3, g3, be3, out, nullptr, nullptr);

    k_poolA<<<BGRAPH * POOL_CH, H>>>(out);
    k_poolB<<<BGRAPH, H>>>(out);
}

// round 7
// speedup vs baseline: 1.4247x; 1.1498x over previous
#include <cuda_runtime.h>
#include <cfloat>
#include <stdint.h>

#define N_NODES 100000
#define N_EDGES 1600000
#define BGRAPH  64
#define DINP    9
#define H       128
#define EPS     1e-5f

#define SCAN_BLK 512
#define SCAN_NB  196   // ceil(100000/512)
#define POOL_CH  16

typedef unsigned u32;

// ---------------- scratch (device globals; no allocation allowed) -----------
// Interleaved bf16 hi/lo storage per node: 128 u32 words.
// word[2p]   = hi bf16 pair p (channels 2p [lo16], 2p+1 [hi16])
// word[2p+1] = lo bf16 pair p
__device__ u32 g_hA[N_NODES * 128];
__device__ u32 g_hB[N_NODES * 128];
__device__ u32 g_ag[N_NODES * 128];
// weights: per layer [c 128][256 words interleaved hi/lo over 128 k-pairs]
__device__ u32 g_W[3 * 128 * 256];
__device__ int g_rowptr[N_NODES + 1];
__device__ int g_col[N_EDGES];
__device__ int g_deg[N_NODES];
__device__ int g_cursor[N_NODES];
__device__ int g_bsum[SCAN_NB];
__device__ int g_start[BGRAPH + 1];
__device__ float g_pp[BGRAPH * POOL_CH * 2 * H];

// ---------------- bf16 helpers ----------------------------------------------
__device__ __forceinline__ u32 bf16rn(float f) {
    u32 u = __float_as_uint(f);
    return (u + 0x7fffu + ((u >> 16) & 1u)) >> 16;
}
__device__ __forceinline__ void bfsplit(float f, u32& hi, u32& lo) {
    hi = bf16rn(f);
    float r = f - __uint_as_float(hi << 16);
    lo = bf16rn(r);
}

#define MMA_BF16(c0,c1,c2,c3,a0,a1,a2,a3,b0,b1) \
    asm volatile("mma.sync.aligned.m16n8k16.row.col.f32.bf16.bf16.f32 " \
        "{%0,%1,%2,%3}, {%4,%5,%6,%7}, {%8,%9}, {%0,%1,%2,%3};\n" \
        : "+f"(c0), "+f"(c1), "+f"(c2), "+f"(c3) \
        : "r"(a0), "r"(a1), "r"(a2), "r"(a3), "r"(b0), "r"(b1))

// ---------------- CSR build -------------------------------------------------
__global__ void k_zero() {
    int i = blockIdx.x * blockDim.x + threadIdx.x;
    if (i < N_NODES) { g_deg[i] = 0; g_cursor[i] = 0; }
}

__global__ void k_deg(const int* __restrict__ dst) {
    int e = blockIdx.x * blockDim.x + threadIdx.x;
    if (e < N_EDGES) atomicAdd(&g_deg[dst[e]], 1);
}

__global__ void k_scan1() {
    __shared__ int sh[SCAN_BLK];
    int t = threadIdx.x;
    int i = blockIdx.x * SCAN_BLK + t;
    int v = (i < N_NODES) ? g_deg[i] : 0;
    sh[t] = v; __syncthreads();
    for (int o = 1; o < SCAN_BLK; o <<= 1) {
        int a = (t >= o) ? sh[t - o] : 0;
        __syncthreads();
        sh[t] += a;
        __syncthreads();
    }
    if (i < N_NODES) g_rowptr[i] = sh[t] - v;
    if (t == SCAN_BLK - 1) g_bsum[blockIdx.x] = sh[t];
}

__global__ void k_scan2() {
    __shared__ int sh[256];
    int t = threadIdx.x;
    int v = (t < SCAN_NB) ? g_bsum[t] : 0;
    sh[t] = v; __syncthreads();
    for (int o = 1; o < 256; o <<= 1) {
        int a = (t >= o) ? sh[t - o] : 0;
        __syncthreads();
        sh[t] += a;
        __syncthreads();
    }
    if (t < SCAN_NB) g_bsum[t] = sh[t] - v;
    if (t == 0) g_rowptr[N_NODES] = N_EDGES;
}

__global__ void k_scan3() {
    int i = blockIdx.x * SCAN_BLK + threadIdx.x;
    if (i < N_NODES) g_rowptr[i] += g_bsum[blockIdx.x];
}

__global__ void k_scatter(const int* __restrict__ src, const int* __restrict__ dst) {
    int e = blockIdx.x * blockDim.x + threadIdx.x;
    if (e < N_EDGES) {
        int d = dst[e];
        int p = atomicAdd(&g_cursor[d], 1);
        g_col[g_rowptr[d] + p] = src[e];
    }
}

// ---------------- weight split (interleaved): W[c][k] = [Wl ; Wr] ------------
__global__ void k_wsplit(const float* __restrict__ Wl1, const float* __restrict__ Wr1,
                         const float* __restrict__ Wl2, const float* __restrict__ Wr2,
                         const float* __restrict__ Wl3, const float* __restrict__ Wr3) {
    int idx = blockIdx.x * blockDim.x + threadIdx.x;   // pair index
    if (idx >= 3 * 128 * 128) return;
    int l = idx / (128 * 128);
    int r = idx % (128 * 128);
    int c = r >> 7;            // 0..127
    int kp = r & 127;          // k-pair
    int k0 = kp * 2;
    const float* Wl = (l == 0) ? Wl1 : (l == 1) ? Wl2 : Wl3;
    const float* Wr = (l == 0) ? Wr1 : (l == 1) ? Wr2 : Wr3;
    float w0 = (k0 < 128) ? Wl[c * 128 + k0] : Wr[c * 128 + k0 - 128];
    float w1 = (k0 + 1 < 128) ? Wl[c * 128 + k0 + 1] : Wr[c * 128 + k0 + 1 - 128];
    u32 h0, l0, h1, l1;
    bfsplit(w0, h0, l0);
    bfsplit(w1, h1, l1);
    size_t base = (size_t)l * 128 * 256 + (size_t)c * 256 + kp * 2;
    *(uint2*)&g_W[base] = make_uint2(h0 | (h1 << 16), l0 | (l1 << 16));
}

// ---------------- node embedder: relu(LN(x @ W0^T + b0)) -> interleaved ------
__global__ void k_embed(const float* __restrict__ x, const float* __restrict__ W0,
                        const float* __restrict__ b0, const float* __restrict__ g0,
                        const float* __restrict__ be0) {
    int gw = (blockIdx.x * blockDim.x + threadIdx.x) >> 5;
    int lane = threadIdx.x & 31;
    if (gw >= N_NODES) return;
    float xd = (lane < DINP) ? x[gw * DINP + lane] : 0.f;
    float xs[DINP];
#pragma unroll
    for (int d = 0; d < DINP; d++) xs[d] = __shfl_sync(0xffffffffu, xd, d);
    float o[4];
#pragma unroll
    for (int j = 0; j < 4; j++) {
        int c = lane * 4 + j;
        float acc = b0[c];
#pragma unroll
        for (int d = 0; d < DINP; d++) acc = fmaf(xs[d], W0[c * DINP + d], acc);
        o[j] = acc;
    }
    float s1 = o[0] + o[1] + o[2] + o[3];
    float s2 = o[0]*o[0] + o[1]*o[1] + o[2]*o[2] + o[3]*o[3];
#pragma unroll
    for (int off = 16; off; off >>= 1) {
        s1 += __shfl_xor_sync(0xffffffffu, s1, off);
        s2 += __shfl_xor_sync(0xffffffffu, s2, off);
    }
    float m  = s1 * (1.f / H);
    float var = fmaxf(s2 * (1.f / H) - m * m, 0.f);
    float rs = rsqrtf(var + EPS);
    u32 hb[4], lb[4];
#pragma unroll
    for (int j = 0; j < 4; j++) {
        int c = lane * 4 + j;
        float v = fmaxf((o[j] - m) * rs * g0[c] + be0[c], 0.f);
        bfsplit(v, hb[j], lb[j]);
    }
    size_t base = (size_t)gw * 128 + lane * 4;
    *(uint4*)&g_hA[base] = make_uint4(hb[0] | (hb[1] << 16), lb[0] | (lb[1] << 16),
                                      hb[2] | (hb[3] << 16), lb[2] | (lb[3] << 16));
}

// ---------------- mean aggregation: warp per node, one LDG.128/edge/lane -----
__global__ void k_agg(const u32* __restrict__ h) {
    int gw = (blockIdx.x * blockDim.x + threadIdx.x) >> 5;
    int lane = threadIdx.x & 31;
    if (gw >= N_NODES) return;
    int s = g_rowptr[gw], e = g_rowptr[gw + 1];
    int lane4 = lane * 4;
    float a0 = 0.f, a1 = 0.f, a2 = 0.f, a3 = 0.f;
    float b0 = 0.f, b1 = 0.f, b2 = 0.f, b3 = 0.f;
    int p = s;
    for (; p + 1 < e; p += 2) {
        int sn0 = __ldg(&g_col[p]);
        int sn1 = __ldg(&g_col[p + 1]);
        uint4 w0 = *(const uint4*)&h[(size_t)sn0 * 128 + lane4];
        uint4 w1 = *(const uint4*)&h[(size_t)sn1 * 128 + lane4];
        a0 += __uint_as_float(w0.x << 16) + __uint_as_float(w0.y << 16);
        a1 += __uint_as_float(w0.x & 0xffff0000u) + __uint_as_float(w0.y & 0xffff0000u);
        a2 += __uint_as_float(w0.z << 16) + __uint_as_float(w0.w << 16);
        a3 += __uint_as_float(w0.z & 0xffff0000u) + __uint_as_float(w0.w & 0xffff0000u);
        b0 += __uint_as_float(w1.x << 16) + __uint_as_float(w1.y << 16);
        b1 += __uint_as_float(w1.x & 0xffff0000u) + __uint_as_float(w1.y & 0xffff0000u);
        b2 += __uint_as_float(w1.z << 16) + __uint_as_float(w1.w << 16);
        b3 += __uint_as_float(w1.z & 0xffff0000u) + __uint_as_float(w1.w & 0xffff0000u);
    }
    if (p < e) {
        int sn = __ldg(&g_col[p]);
        uint4 w = *(const uint4*)&h[(size_t)sn * 128 + lane4];
        a0 += __uint_as_float(w.x << 16) + __uint_as_float(w.y << 16);
        a1 += __uint_as_float(w.x & 0xffff0000u) + __uint_as_float(w.y & 0xffff0000u);
        a2 += __uint_as_float(w.z << 16) + __uint_as_float(w.w << 16);
        a3 += __uint_as_float(w.z & 0xffff0000u) + __uint_as_float(w.w & 0xffff0000u);
    }
    float inv = 1.f / fmaxf((float)(e - s), 1.f);
    a0 = (a0 + b0) * inv; a1 = (a1 + b1) * inv;
    a2 = (a2 + b2) * inv; a3 = (a3 + b3) * inv;
    u32 h0, l0, h1, l1, h2, l2, h3, l3;
    bfsplit(a0, h0, l0); bfsplit(a1, h1, l1);
    bfsplit(a2, h2, l2); bfsplit(a3, h3, l3);
    *(uint4*)&g_ag[(size_t)gw * 128 + lane4] =
        make_uint4(h0 | (h1 << 16), l0 | (l1 << 16), h2 | (h3 << 16), l2 | (l3 << 16));
}

// ---------------- tensor-core layer: bf16x3 MMA + LayerNorm + ReLU ----------
__global__ void __launch_bounds__(256, 2) k_layer(
    const u32* __restrict__ ag, const u32* __restrict__ h,
    const u32* __restrict__ W,
    const float* __restrict__ bl, const float* __restrict__ gg,
    const float* __restrict__ be,
    float* __restrict__ outF, u32* __restrict__ outI)
{
    __shared__ __align__(16) u32 AsHi[128 * 16];
    __shared__ __align__(16) u32 AsLo[128 * 16];
    __shared__ __align__(16) u32 WsHi[128 * 16];
    __shared__ __align__(16) u32 WsLo[128 * 16];
    __shared__ float sBl[128], sGg[128], sBe[128];

    int t = threadIdx.x;
    int lane = t & 31;
    int wid = t >> 5;
    int g  = lane >> 2;     // 0..7
    int t2 = lane & 3;      // 0..3
    int m0 = wid * 16;
    int nodeBase = blockIdx.x * 128;

    if (t < 128) { sBl[t] = bl[t]; sGg[t] = gg[t]; sBe[t] = be[t]; }

    float acc[16][4];
#pragma unroll
    for (int nt = 0; nt < 16; nt++)
#pragma unroll
        for (int j = 0; j < 4; j++) acc[nt][j] = 0.f;

#pragma unroll 1
    for (int kk = 0; kk < 256; kk += 32) {
        const u32* feat; int koff;
        if (kk < 128) { feat = ag; koff = kk; }
        else          { feat = h;  koff = kk - 128; }
#pragma unroll
        for (int it = 0; it < 8; it++) {
            int i = it * 256 + t;           // 0..2047
            int row = i >> 4;
            int j32 = i & 15;
            int blk = j32 >> 3, j = j32 & 7;
            int pj = (j < 4) ? (2 * j) : (2 * j - 7);
            int sIdx = (row * 16 + blk * 8 + pj) ^ (((row >> 1) & 1) << 3);
            int gnode = nodeBase + row;
            uint2 v = make_uint2(0u, 0u);
            if (gnode < N_NODES)
                v = *(const uint2*)&feat[(size_t)gnode * 128 + koff + 2 * j32];
            AsHi[sIdx] = v.x; AsLo[sIdx] = v.y;
            uint2 w = *(const uint2*)&W[(size_t)row * 256 + kk + 2 * j32];
            WsHi[sIdx] = w.x; WsLo[sIdx] = w.y;
        }
        __syncthreads();

#pragma unroll
        for (int blk = 0; blk < 2; blk++) {
            int rA = m0 + g, rB = m0 + g + 8;
            int iA = (rA * 16 + blk * 8 + 2 * t2) ^ (((rA >> 1) & 1) << 3);
            int iB = (rB * 16 + blk * 8 + 2 * t2) ^ (((rB >> 1) & 1) << 3);
            uint2 a02h = *(const uint2*)&AsHi[iA];
            uint2 a13h = *(const uint2*)&AsHi[iB];
            uint2 a02l = *(const uint2*)&AsLo[iA];
            uint2 a13l = *(const uint2*)&AsLo[iB];
#pragma unroll
            for (int nt = 0; nt < 16; nt++) {
                int c = nt * 8 + g;
                int iW = (c * 16 + blk * 8 + 2 * t2) ^ (((c >> 1) & 1) << 3);
                uint2 bh = *(const uint2*)&WsHi[iW];
                uint2 blo = *(const uint2*)&WsLo[iW];
                MMA_BF16(acc[nt][0], acc[nt][1], acc[nt][2], acc[nt][3],
                         a02h.x, a13h.x, a02h.y, a13h.y, bh.x, bh.y);
                MMA_BF16(acc[nt][0], acc[nt][1], acc[nt][2], acc[nt][3],
                         a02h.x, a13h.x, a02h.y, a13h.y, blo.x, blo.y);
                MMA_BF16(acc[nt][0], acc[nt][1], acc[nt][2], acc[nt][3],
                         a02l.x, a13l.x, a02l.y, a13l.y, bh.x, bh.y);
            }
        }
        __syncthreads();
    }

    // ---- epilogue ----
    float sA1 = 0.f, sA2 = 0.f, sB1 = 0.f, sB2 = 0.f;
#pragma unroll
    for (int nt = 0; nt < 16; nt++) {
        int c0 = nt * 8 + 2 * t2;
        float b0 = sBl[c0], b1 = sBl[c0 + 1];
        float va0 = acc[nt][0] + b0, va1 = acc[nt][1] + b1;
        float vb0 = acc[nt][2] + b0, vb1 = acc[nt][3] + b1;
        sA1 += va0 + va1; sA2 += va0 * va0 + va1 * va1;
        sB1 += vb0 + vb1; sB2 += vb0 * vb0 + vb1 * vb1;
    }
#pragma unroll
    for (int off = 1; off <= 2; off <<= 1) {
        sA1 += __shfl_xor_sync(0xffffffffu, sA1, off);
        sA2 += __shfl_xor_sync(0xffffffffu, sA2, off);
        sB1 += __shfl_xor_sync(0xffffffffu, sB1, off);
        sB2 += __shfl_xor_sync(0xffffffffu, sB2, off);
    }
    float mA = sA1 * (1.f / H);
    float vA = fmaxf(sA2 * (1.f / H) - mA * mA, 0.f);
    float rsA = rsqrtf(vA + EPS);
    float mB = sB1 * (1.f / H);
    float vB = fmaxf(sB2 * (1.f / H) - mB * mB, 0.f);
    float rsB = rsqrtf(vB + EPS);

    int gA = nodeBase + m0 + g;
    int gB = gA + 8;
    bool wA = gA < N_NODES, wB = gB < N_NODES;

#pragma unroll
    for (int nt = 0; nt < 16; nt++) {
        int c0 = nt * 8 + 2 * t2;
        float b0 = sBl[c0], b1 = sBl[c0 + 1];
        float gg0 = sGg[c0], gg1 = sGg[c0 + 1];
        float be0 = sBe[c0], be1 = sBe[c0 + 1];
        float oa0 = fmaxf((acc[nt][0] + b0 - mA) * rsA * gg0 + be0, 0.f);
        float oa1 = fmaxf((acc[nt][1] + b1 - mA) * rsA * gg1 + be1, 0.f);
        float ob0 = fmaxf((acc[nt][2] + b0 - mB) * rsB * gg0 + be0, 0.f);
        float ob1 = fmaxf((acc[nt][3] + b1 - mB) * rsB * gg1 + be1, 0.f);
        if (outF) {
            if (wA) *(float2*)&outF[(size_t)gA * 128 + c0] = make_float2(oa0, oa1);
            if (wB) *(float2*)&outF[(size_t)gB * 128 + c0] = make_float2(ob0, ob1);
        } else {
            u32 h0, l0, h1, l1;
            if (wA) {
                bfsplit(oa0, h0, l0); bfsplit(oa1, h1, l1);
                *(uint2*)&outI[(size_t)gA * 128 + c0] =
                    make_uint2(h0 | (h1 << 16), l0 | (l1 << 16));
            }
            if (wB) {
                bfsplit(ob0, h0, l0); bfsplit(ob1, h1, l1);
                *(uint2*)&outI[(size_t)gB * 128 + c0] =
                    make_uint2(h0 | (h1 << 16), l0 | (l1 << 16));
            }
        }
    }
}

// ---------------- pooling (two-stage) ---------------------------------------
__global__ void k_startk(const int* __restrict__ batch) {
    int i = blockIdx.x * blockDim.x + threadIdx.x;
    if (i >= N_NODES) return;
    int b  = batch[i];
    int bp = (i == 0) ? -1 : batch[i - 1];
    for (int g = bp + 1; g <= b; g++) g_start[g] = i;
    if (i == N_NODES - 1)
        for (int g = b + 1; g <= BGRAPH; g++) g_start[g] = N_NODES;
}

__global__ void k_poolA(const float* __restrict__ ne) {
    int b  = blockIdx.x / POOL_CH;
    int ch = blockIdx.x % POOL_CH;
    int c  = threadIdx.x;
    int s = g_start[b], e = g_start[b + 1];
    int len = e - s;
    int cs = s + (int)(((long long)len * ch) / POOL_CH);
    int ce = s + (int)(((long long)len * (ch + 1)) / POOL_CH);
    float sum = 0.f, mx = -FLT_MAX;
    for (int n = cs; n < ce; n++) {
        float v = ne[(size_t)n * H + c];
        sum += v;
        mx = fmaxf(mx, v);
    }
    size_t base = ((size_t)(b * POOL_CH + ch)) * 2 * H;
    g_pp[base + c]     = sum;
    g_pp[base + H + c] = mx;
}

__global__ void k_poolB(float* __restrict__ out) {
    int b = blockIdx.x;
    int c = threadIdx.x;
    int s = g_start[b], e = g_start[b + 1];
    float sum = 0.f, mx = -FLT_MAX;
#pragma unroll
    for (int ch = 0; ch < POOL_CH; ch++) {
        size_t base = ((size_t)(b * POOL_CH + ch)) * 2 * H;
        sum += g_pp[base + c];
        mx = fmaxf(mx, g_pp[base + H + c]);
    }
    float cnt = (float)(e - s);
    size_t gbase = (size_t)N_NODES * H + (size_t)b * 2 * H;
    out[gbase + c]     = sum / fmaxf(cnt, 1.f);
    out[gbase + H + c] = mx;
}

// ---------------- launch ----------------------------------------------------
extern "C" void kernel_launch(void* const* d_in, const int* in_sizes, int n_in,
                              void* d_out, int out_size) {
    const float* x     = (const float*)d_in[0];
    const int*   ei    = (const int*)  d_in[1];
    const int*   batch = (const int*)  d_in[2];
    const float* W0  = (const float*)d_in[3];
    const float* b0  = (const float*)d_in[4];
    const float* g0  = (const float*)d_in[5];
    const float* be0 = (const float*)d_in[6];
    const float* Wl1 = (const float*)d_in[7];
    const float* bl1 = (const float*)d_in[8];
    const float* Wr1 = (const float*)d_in[9];
    const float* g1  = (const float*)d_in[10];
    const float* be1 = (const float*)d_in[11];
    const float* Wl2 = (const float*)d_in[12];
    const float* bl2 = (const float*)d_in[13];
    const float* Wr2 = (const float*)d_in[14];
    const float* g2  = (const float*)d_in[15];
    const float* be2 = (const float*)d_in[16];
    const float* Wl3 = (const float*)d_in[17];
    const float* bl3 = (const float*)d_in[18];
    const float* Wr3 = (const float*)d_in[19];
    const float* g3  = (const float*)d_in[20];
    const float* be3 = (const float*)d_in[21];

    const int* src = ei;
    const int* dst = ei + N_EDGES;
    float* out = (float*)d_out;

    u32 *hA, *hB, *ag, *W;
    cudaGetSymbolAddress((void**)&hA, g_hA);
    cudaGetSymbolAddress((void**)&hB, g_hB);
    cudaGetSymbolAddress((void**)&ag, g_ag);
    cudaGetSymbolAddress((void**)&W, g_W);

    const int nodeBlocks = (N_NODES + 255) / 256;
    const int edgeBlocks = (N_EDGES + 255) / 256;
    const int warpBlocks = (N_NODES + 7) / 8;          // 8 warps/block
    const int tileBlocks = (N_NODES + 127) / 128;      // 782

    // CSR build (every launch — caching is forbidden)
    k_zero<<<nodeBlocks, 256>>>();
    k_deg<<<edgeBlocks, 256>>>(dst);
    k_scan1<<<SCAN_NB, SCAN_BLK>>>();
    k_scan2<<<1, 256>>>();
    k_scan3<<<SCAN_NB, SCAN_BLK>>>();
    k_scatter<<<edgeBlocks, 256>>>(src, dst);

    k_wsplit<<<(3 * 128 * 128 + 255) / 256, 256>>>(Wl1, Wr1, Wl2, Wr2, Wl3, Wr3);

    k_embed<<<warpBlocks, 256>>>(x, W0, b0, g0, be0);
    k_startk<<<nodeBlocks, 256>>>(batch);

    // layer 1: A -> B
    k_agg<<<warpBlocks, 256>>>(hA);
    k_layer<<<tileBlocks, 256>>>(ag, hA, W + 0 * 128 * 256, bl1, g1, be1, nullptr, hB);
    // layer 2: B -> A
    k_agg<<<warpBlocks, 256>>>(hB);
    k_layer<<<tileBlocks, 256>>>(ag, hB, W + 1 * 128 * 256, bl2, g2, be2, nullptr, hA);
    // layer 3: A -> out (fp32 node_embed)
    k_agg<<<warpBlocks, 256>>>(hA);
    k_layer<<<tileBlocks, 256>>>(ag, hA, W + 2 * 128 * 256, bl3, g3, be3, out, nullptr);

    k_poolA<<<BGRAPH * POOL_CH, H>>>(out);
    k_poolB<<<BGRAPH, H>>>(out);
}

// round 11
// speedup vs baseline: 1.4288x; 1.0029x over previous
#include <cuda_runtime.h>
#include <cfloat>
#include <stdint.h>

#define N_NODES 100000
#define N_EDGES 1600000
#define BGRAPH  64
#define DINP    9
#define H       128
#define EPS     1e-5f

#define SCAN_BLK 512
#define SCAN_NB  196   // ceil(100000/512)
#define POOL_CH  16

typedef unsigned u32;

// ---------------- scratch (device globals; no allocation allowed) -----------
// Interleaved bf16 hi/lo storage per node: 128 u32 words.
// word[2p] = hi pair p (ch 2p lo16, 2p+1 hi16); word[2p+1] = lo pair p.
__device__ u32 g_hA[N_NODES * 128];
__device__ u32 g_hB[N_NODES * 128];
__device__ u32 g_ag[N_NODES * 128];
__device__ u32 g_W[3 * 128 * 256];      // per layer [c 128][256 words hi/lo interleaved]
__device__ int g_rowptr[N_NODES + 1];
__device__ int g_col[N_EDGES];
__device__ int g_deg[N_NODES];
__device__ int g_cursor[N_NODES];
__device__ int g_bsum[SCAN_NB];
__device__ int g_start[BGRAPH + 1];
__device__ float g_pp[BGRAPH * POOL_CH * 2 * H];

// ---------------- bf16 helpers ----------------------------------------------
__device__ __forceinline__ u32 bf16rn(float f) {
    u32 u = __float_as_uint(f);
    return (u + 0x7fffu + ((u >> 16) & 1u)) >> 16;
}
__device__ __forceinline__ void bfsplit(float f, u32& hi, u32& lo) {
    hi = bf16rn(f);
    float r = f - __uint_as_float(hi << 16);
    lo = bf16rn(r);
}

#define MMA_BF16(c0,c1,c2,c3,a0,a1,a2,a3,b0,b1) \
    asm volatile("mma.sync.aligned.m16n8k16.row.col.f32.bf16.bf16.f32 " \
        "{%0,%1,%2,%3}, {%4,%5,%6,%7}, {%8,%9}, {%0,%1,%2,%3};\n" \
        : "+f"(c0), "+f"(c1), "+f"(c2), "+f"(c3) \
        : "r"(a0), "r"(a1), "r"(a2), "r"(a3), "r"(b0), "r"(b1))

// ---------------- CSR build -------------------------------------------------
__global__ void k_zero() {
    int i = blockIdx.x * blockDim.x + threadIdx.x;
    if (i < N_NODES) { g_deg[i] = 0; g_cursor[i] = 0; }
}

__global__ void k_deg(const int* __restrict__ dst) {
    int e = blockIdx.x * blockDim.x + threadIdx.x;
    if (e < N_EDGES) atomicAdd(&g_deg[dst[e]], 1);
}

__global__ void k_scan1() {
    __shared__ int sh[SCAN_BLK];
    int t = threadIdx.x;
    int i = blockIdx.x * SCAN_BLK + t;
    int v = (i < N_NODES) ? g_deg[i] : 0;
    sh[t] = v; __syncthreads();
    for (int o = 1; o < SCAN_BLK; o <<= 1) {
        int a = (t >= o) ? sh[t - o] : 0;
        __syncthreads();
        sh[t] += a;
        __syncthreads();
    }
    if (i < N_NODES) g_rowptr[i] = sh[t] - v;
    if (t == SCAN_BLK - 1) g_bsum[blockIdx.x] = sh[t];
}

__global__ void k_scan2() {
    __shared__ int sh[256];
    int t = threadIdx.x;
    int v = (t < SCAN_NB) ? g_bsum[t] : 0;
    sh[t] = v; __syncthreads();
    for (int o = 1; o < 256; o <<= 1) {
        int a = (t >= o) ? sh[t - o] : 0;
        __syncthreads();
        sh[t] += a;
        __syncthreads();
    }
    if (t < SCAN_NB) g_bsum[t] = sh[t] - v;
    if (t == 0) g_rowptr[N_NODES] = N_EDGES;
}

__global__ void k_scan3() {
    int i = blockIdx.x * SCAN_BLK + threadIdx.x;
    if (i < N_NODES) g_rowptr[i] += g_bsum[blockIdx.x];
}

__global__ void k_scatter(const int* __restrict__ src, const int* __restrict__ dst) {
    int e = blockIdx.x * blockDim.x + threadIdx.x;
    if (e < N_EDGES) {
        int d = dst[e];
        int p = atomicAdd(&g_cursor[d], 1);
        g_col[g_rowptr[d] + p] = src[e];
    }
}

// ---------------- weight split (interleaved): W[c][k] = [Wl ; Wr] ------------
__global__ void k_wsplit(const float* __restrict__ Wl1, const float* __restrict__ Wr1,
                         const float* __restrict__ Wl2, const float* __restrict__ Wr2,
                         const float* __restrict__ Wl3, const float* __restrict__ Wr3) {
    int idx = blockIdx.x * blockDim.x + threadIdx.x;   // pair index
    if (idx >= 3 * 128 * 128) return;
    int l = idx / (128 * 128);
    int r = idx % (128 * 128);
    int c = r >> 7;            // 0..127
    int kp = r & 127;          // k-pair
    int k0 = kp * 2;
    const float* Wl = (l == 0) ? Wl1 : (l == 1) ? Wl2 : Wl3;
    const float* Wr = (l == 0) ? Wr1 : (l == 1) ? Wr2 : Wr3;
    float w0 = (k0 < 128) ? Wl[c * 128 + k0] : Wr[c * 128 + k0 - 128];
    float w1 = (k0 + 1 < 128) ? Wl[c * 128 + k0 + 1] : Wr[c * 128 + k0 + 1 - 128];
    u32 h0, l0, h1, l1;
    bfsplit(w0, h0, l0);
    bfsplit(w1, h1, l1);
    size_t base = (size_t)l * 128 * 256 + (size_t)c * 256 + kp * 2;
    *(uint2*)&g_W[base] = make_uint2(h0 | (h1 << 16), l0 | (l1 << 16));
}

// ---------------- node embedder: relu(LN(x @ W0^T + b0)) -> interleaved ------
__global__ void k_embed(const float* __restrict__ x, const float* __restrict__ W0,
                        const float* __restrict__ b0, const float* __restrict__ g0,
                        const float* __restrict__ be0) {
    int gw = (blockIdx.x * blockDim.x + threadIdx.x) >> 5;
    int lane = threadIdx.x & 31;
    if (gw >= N_NODES) return;
    float xd = (lane < DINP) ? x[gw * DINP + lane] : 0.f;
    float xs[DINP];
#pragma unroll
    for (int d = 0; d < DINP; d++) xs[d] = __shfl_sync(0xffffffffu, xd, d);
    float o[4];
#pragma unroll
    for (int j = 0; j < 4; j++) {
        int c = lane * 4 + j;
        float acc = b0[c];
#pragma unroll
        for (int d = 0; d < DINP; d++) acc = fmaf(xs[d], W0[c * DINP + d], acc);
        o[j] = acc;
    }
    float s1 = o[0] + o[1] + o[2] + o[3];
    float s2 = o[0]*o[0] + o[1]*o[1] + o[2]*o[2] + o[3]*o[3];
#pragma unroll
    for (int off = 16; off; off >>= 1) {
        s1 += __shfl_xor_sync(0xffffffffu, s1, off);
        s2 += __shfl_xor_sync(0xffffffffu, s2, off);
    }
    float m  = s1 * (1.f / H);
    float var = fmaxf(s2 * (1.f / H) - m * m, 0.f);
    float rs = rsqrtf(var + EPS);
    u32 hb[4], lb[4];
#pragma unroll
    for (int j = 0; j < 4; j++) {
        int c = lane * 4 + j;
        float v = fmaxf((o[j] - m) * rs * g0[c] + be0[c], 0.f);
        bfsplit(v, hb[j], lb[j]);
    }
    size_t base = (size_t)gw * 128 + lane * 4;
    *(uint4*)&g_hA[base] = make_uint4(hb[0] | (hb[1] << 16), lb[0] | (lb[1] << 16),
                                      hb[2] | (hb[3] << 16), lb[2] | (lb[3] << 16));
}

// ---------------- mean aggregation: warp per node, 4-way edge unroll ---------
__global__ void k_agg(const u32* __restrict__ h) {
    int gw = (blockIdx.x * blockDim.x + threadIdx.x) >> 5;
    int lane = threadIdx.x & 31;
    if (gw >= N_NODES) return;
    int s = g_rowptr[gw], e = g_rowptr[gw + 1];
    int lane4 = lane * 4;
    float a0 = 0.f, a1 = 0.f, a2 = 0.f, a3 = 0.f;
    float b0 = 0.f, b1 = 0.f, b2 = 0.f, b3 = 0.f;
    int p = s;
    for (; p + 3 < e; p += 4) {
        int sn0 = __ldg(&g_col[p]);
        int sn1 = __ldg(&g_col[p + 1]);
        int sn2 = __ldg(&g_col[p + 2]);
        int sn3 = __ldg(&g_col[p + 3]);
        uint4 w0 = *(const uint4*)&h[(size_t)sn0 * 128 + lane4];
        uint4 w1 = *(const uint4*)&h[(size_t)sn1 * 128 + lane4];
        uint4 w2 = *(const uint4*)&h[(size_t)sn2 * 128 + lane4];
        uint4 w3 = *(const uint4*)&h[(size_t)sn3 * 128 + lane4];
        a0 += __uint_as_float(w0.x << 16) + __uint_as_float(w0.y << 16);
        a1 += __uint_as_float(w0.x & 0xffff0000u) + __uint_as_float(w0.y & 0xffff0000u);
        a2 += __uint_as_float(w0.z << 16) + __uint_as_float(w0.w << 16);
        a3 += __uint_as_float(w0.z & 0xffff0000u) + __uint_as_float(w0.w & 0xffff0000u);
        b0 += __uint_as_float(w1.x << 16) + __uint_as_float(w1.y << 16);
        b1 += __uint_as_float(w1.x & 0xffff0000u) + __uint_as_float(w1.y & 0xffff0000u);
        b2 += __uint_as_float(w1.z << 16) + __uint_as_float(w1.w << 16);
        b3 += __uint_as_float(w1.z & 0xffff0000u) + __uint_as_float(w1.w & 0xffff0000u);
        a0 += __uint_as_float(w2.x << 16) + __uint_as_float(w2.y << 16);
        a1 += __uint_as_float(w2.x & 0xffff0000u) + __uint_as_float(w2.y & 0xffff0000u);
        a2 += __uint_as_float(w2.z << 16) + __uint_as_float(w2.w << 16);
        a3 += __uint_as_float(w2.z & 0xffff0000u) + __uint_as_float(w2.w & 0xffff0000u);
        b0 += __uint_as_float(w3.x << 16) + __uint_as_float(w3.y << 16);
        b1 += __uint_as_float(w3.x & 0xffff0000u) + __uint_as_float(w3.y & 0xffff0000u);
        b2 += __uint_as_float(w3.z << 16) + __uint_as_float(w3.w << 16);
        b3 += __uint_as_float(w3.z & 0xffff0000u) + __uint_as_float(w3.w & 0xffff0000u);
    }
    for (; p < e; p++) {
        int sn = __ldg(&g_col[p]);
        uint4 w = *(const uint4*)&h[(size_t)sn * 128 + lane4];
        a0 += __uint_as_float(w.x << 16) + __uint_as_float(w.y << 16);
        a1 += __uint_as_float(w.x & 0xffff0000u) + __uint_as_float(w.y & 0xffff0000u);
        a2 += __uint_as_float(w.z << 16) + __uint_as_float(w.w << 16);
        a3 += __uint_as_float(w.z & 0xffff0000u) + __uint_as_float(w.w & 0xffff0000u);
    }
    float inv = 1.f / fmaxf((float)(e - s), 1.f);
    a0 = (a0 + b0) * inv; a1 = (a1 + b1) * inv;
    a2 = (a2 + b2) * inv; a3 = (a3 + b3) * inv;
    u32 h0, l0, h1, l1, h2, l2, h3, l3;
    bfsplit(a0, h0, l0); bfsplit(a1, h1, l1);
    bfsplit(a2, h2, l2); bfsplit(a3, h3, l3);
    *(uint4*)&g_ag[(size_t)gw * 128 + lane4] =
        make_uint4(h0 | (h1 << 16), l0 | (l1 << 16), h2 | (h3 << 16), l2 | (l3 << 16));
}

// ---------------- tensor-core layer: bf16x3 MMA + LayerNorm + ReLU ----------
__global__ void __launch_bounds__(256, 2) k_layer(
    const u32* __restrict__ ag, const u32* __restrict__ h,
    const u32* __restrict__ W,
    const float* __restrict__ bl, const float* __restrict__ gg,
    const float* __restrict__ be,
    float* __restrict__ outF, u32* __restrict__ outI)
{
    __shared__ __align__(16) u32 AsHi[128 * 16];
    __shared__ __align__(16) u32 AsLo[128 * 16];
    __shared__ __align__(16) u32 WsHi[128 * 16];
    __shared__ __align__(16) u32 WsLo[128 * 16];
    __shared__ float sBl[128], sGg[128], sBe[128];

    int t = threadIdx.x;
    int lane = t & 31;
    int wid = t >> 5;
    int g  = lane >> 2;     // 0..7
    int t2 = lane & 3;      // 0..3
    int m0 = wid * 16;
    int nodeBase = blockIdx.x * 128;

    if (t < 128) { sBl[t] = bl[t]; sGg[t] = gg[t]; sBe[t] = be[t]; }

    float acc[16][4];
#pragma unroll
    for (int nt = 0; nt < 16; nt++)
#pragma unroll
        for (int j = 0; j < 4; j++) acc[nt][j] = 0.f;

#pragma unroll 1
    for (int kk = 0; kk < 256; kk += 32) {
        const u32* feat; int koff;
        if (kk < 128) { feat = ag; koff = kk; }
        else          { feat = h;  koff = kk - 128; }
#pragma unroll
        for (int it = 0; it < 8; it++) {
            int i = it * 256 + t;           // 0..2047
            int row = i >> 4;
            int j32 = i & 15;
            int blk = j32 >> 3, j = j32 & 7;
            int pj = (j < 4) ? (2 * j) : (2 * j - 7);
            int sIdx = (row * 16 + blk * 8 + pj) ^ (((row >> 1) & 1) << 3);
            int gnode = nodeBase + row;
            uint2 v = make_uint2(0u, 0u);
            if (gnode < N_NODES)
                v = *(const uint2*)&feat[(size_t)gnode * 128 + koff + 2 * j32];
            AsHi[sIdx] = v.x; AsLo[sIdx] = v.y;
            uint2 w = *(const uint2*)&W[(size_t)row * 256 + kk + 2 * j32];
            WsHi[sIdx] = w.x; WsLo[sIdx] = w.y;
        }
        __syncthreads();

#pragma unroll
        for (int blk = 0; blk < 2; blk++) {
            int rA = m0 + g, rB = m0 + g + 8;
            int iA = (rA * 16 + blk * 8 + 2 * t2) ^ (((rA >> 1) & 1) << 3);
            int iB = (rB * 16 + blk * 8 + 2 * t2) ^ (((rB >> 1) & 1) << 3);
            uint2 a02h = *(const uint2*)&AsHi[iA];
            uint2 a13h = *(const uint2*)&AsHi[iB];
            uint2 a02l = *(const uint2*)&AsLo[iA];
            uint2 a13l = *(const uint2*)&AsLo[iB];
#pragma unroll
            for (int nt = 0; nt < 16; nt++) {
                int c = nt * 8 + g;
                int iW = (c * 16 + blk * 8 + 2 * t2) ^ (((c >> 1) & 1) << 3);
                uint2 bh = *(const uint2*)&WsHi[iW];
                uint2 blo = *(const uint2*)&WsLo[iW];
                MMA_BF16(acc[nt][0], acc[nt][1], acc[nt][2], acc[nt][3],
                         a02h.x, a13h.x, a02h.y, a13h.y, bh.x, bh.y);
                MMA_BF16(acc[nt][0], acc[nt][1], acc[nt][2], acc[nt][3],
                         a02h.x, a13h.x, a02h.y, a13h.y, blo.x, blo.y);
                MMA_BF16(acc[nt][0], acc[nt][1], acc[nt][2], acc[nt][3],
                         a02l.x, a13l.x, a02l.y, a13l.y, bh.x, bh.y);
            }
        }
        __syncthreads();
    }

    // ---- epilogue ----
    float sA1 = 0.f, sA2 = 0.f, sB1 = 0.f, sB2 = 0.f;
#pragma unroll
    for (int nt = 0; nt < 16; nt++) {
        int c0 = nt * 8 + 2 * t2;
        float b0 = sBl[c0], b1 = sBl[c0 + 1];
        float va0 = acc[nt][0] + b0, va1 = acc[nt][1] + b1;
        float vb0 = acc[nt][2] + b0, vb1 = acc[nt][3] + b1;
        sA1 += va0 + va1; sA2 += va0 * va0 + va1 * va1;
        sB1 += vb0 + vb1; sB2 += vb0 * vb0 + vb1 * vb1;
    }
#pragma unroll
    for (int off = 1; off <= 2; off <<= 1) {
        sA1 += __shfl_xor_sync(0xffffffffu, sA1, off);
        sA2 += __shfl_xor_sync(0xffffffffu, sA2, off);
        sB1 += __shfl_xor_sync(0xffffffffu, sB1, off);
        sB2 += __shfl_xor_sync(0xffffffffu, sB2, off);
    }
    float mA = sA1 * (1.f / H);
    float vA = fmaxf(sA2 * (1.f / H) - mA * mA, 0.f);
    float rsA = rsqrtf(vA + EPS);
    float mB = sB1 * (1.f / H);
    float vB = fmaxf(sB2 * (1.f / H) - mB * mB, 0.f);
    float rsB = rsqrtf(vB + EPS);

    int gA = nodeBase + m0 + g;
    int gB = gA + 8;
    bool wA = gA < N_NODES, wB = gB < N_NODES;

#pragma unroll
    for (int nt = 0; nt < 16; nt++) {
        int c0 = nt * 8 + 2 * t2;
        float b0 = sBl[c0], b1 = sBl[c0 + 1];
        float gg0 = sGg[c0], gg1 = sGg[c0 + 1];
        float be0 = sBe[c0], be1 = sBe[c0 + 1];
        float oa0 = fmaxf((acc[nt][0] + b0 - mA) * rsA * gg0 + be0, 0.f);
        float oa1 = fmaxf((acc[nt][1] + b1 - mA) * rsA * gg1 + be1, 0.f);
        float ob0 = fmaxf((acc[nt][2] + b0 - mB) * rsB * gg0 + be0, 0.f);
        float ob1 = fmaxf((acc[nt][3] + b1 - mB) * rsB * gg1 + be1, 0.f);
        if (outF) {
            if (wA) *(float2*)&outF[(size_t)gA * 128 + c0] = make_float2(oa0, oa1);
            if (wB) *(float2*)&outF[(size_t)gB * 128 + c0] = make_float2(ob0, ob1);
        } else {
            u32 h0, l0, h1, l1;
            if (wA) {
                bfsplit(oa0, h0, l0); bfsplit(oa1, h1, l1);
                *(uint2*)&outI[(size_t)gA * 128 + c0] =
                    make_uint2(h0 | (h1 << 16), l0 | (l1 << 16));
            }
            if (wB) {
                bfsplit(ob0, h0, l0); bfsplit(ob1, h1, l1);
                *(uint2*)&outI[(size_t)gB * 128 + c0] =
                    make_uint2(h0 | (h1 << 16), l0 | (l1 << 16));
            }
        }
    }
}

// ---------------- pooling (two-stage) ---------------------------------------
__global__ void k_startk(const int* __restrict__ batch) {
    int i = blockIdx.x * blockDim.x + threadIdx.x;
    if (i >= N_NODES) return;
    int b  = batch[i];
    int bp = (i == 0) ? -1 : batch[i - 1];
    for (int g = bp + 1; g <= b; g++) g_start[g] = i;
    if (i == N_NODES - 1)
        for (int g = b + 1; g <= BGRAPH; g++) g_start[g] = N_NODES;
}

__global__ void k_poolA(const float* __restrict__ ne) {
    int b  = blockIdx.x / POOL_CH;
    int ch = blockIdx.x % POOL_CH;
    int c  = threadIdx.x;
    int s = g_start[b], e = g_start[b + 1];
    int len = e - s;
    int cs = s + (int)(((long long)len * ch) / POOL_CH);
    int ce = s + (int)(((long long)len * (ch + 1)) / POOL_CH);
    float sum = 0.f, mx = -FLT_MAX;
    for (int n = cs; n < ce; n++) {
        float v = ne[(size_t)n * H + c];
        sum += v;
        mx = fmaxf(mx, v);
    }
    size_t base = ((size_t)(b * POOL_CH + ch)) * 2 * H;
    g_pp[base + c]     = sum;
    g_pp[base + H + c] = mx;
}

__global__ void k_poolB(float* __restrict__ out) {
    int b = blockIdx.x;
    int c = threadIdx.x;
    int s = g_start[b], e = g_start[b + 1];
    float sum = 0.f, mx = -FLT_MAX;
#pragma unroll
    for (int ch = 0; ch < POOL_CH; ch++) {
        size_t base = ((size_t)(b * POOL_CH + ch)) * 2 * H;
        sum += g_pp[base + c];
        mx = fmaxf(mx, g_pp[base + H + c]);
    }
    float cnt = (float)(e - s);
    size_t gbase = (size_t)N_NODES * H + (size_t)b * 2 * H;
    out[gbase + c]     = sum / fmaxf(cnt, 1.f);
    out[gbase + H + c] = mx;
}

// ---------------- launch ----------------------------------------------------
extern "C" void kernel_launch(void* const* d_in, const int* in_sizes, int n_in,
                              void* d_out, int out_size) {
    const float* x     = (const float*)d_in[0];
    const int*   ei    = (const int*)  d_in[1];
    const int*   batch = (const int*)  d_in[2];
    const float* W0  = (const float*)d_in[3];
    const float* b0  = (const float*)d_in[4];
    const float* g0  = (const float*)d_in[5];
    const float* be0 = (const float*)d_in[6];
    const float* Wl1 = (const float*)d_in[7];
    const float* bl1 = (const float*)d_in[8];
    const float* Wr1 = (const float*)d_in[9];
    const float* g1  = (const float*)d_in[10];
    const float* be1 = (const float*)d_in[11];
    const float* Wl2 = (const float*)d_in[12];
    const float* bl2 = (const float*)d_in[13];
    const float* Wr2 = (const float*)d_in[14];
    const float* g2  = (const float*)d_in[15];
    const float* be2 = (const float*)d_in[16];
    const float* Wl3 = (const float*)d_in[17];
    const float* bl3 = (const float*)d_in[18];
    const float* Wr3 = (const float*)d_in[19];
    const float* g3  = (const float*)d_in[20];
    const float* be3 = (const float*)d_in[21];

    const int* src = ei;
    const int* dst = ei + N_EDGES;
    float* out = (float*)d_out;

    u32 *hA, *hB, *ag, *W;
    cudaGetSymbolAddress((void**)&hA, g_hA);
    cudaGetSymbolAddress((void**)&hB, g_hB);
    cudaGetSymbolAddress((void**)&ag, g_ag);
    cudaGetSymbolAddress((void**)&W, g_W);

    const int nodeBlocks = (N_NODES + 255) / 256;
    const int edgeBlocks = (N_EDGES + 255) / 256;
    const int warpBlocks = (N_NODES + 7) / 8;          // 8 warps/block
    const int tileBlocks = (N_NODES + 127) / 128;      // 782

    // CSR build (every launch — caching is forbidden)
    k_zero<<<nodeBlocks, 256>>>();
    k_deg<<<edgeBlocks, 256>>>(dst);
    k_scan1<<<SCAN_NB, SCAN_BLK>>>();
    k_scan2<<<1, 256>>>();
    k_scan3<<<SCAN_NB, SCAN_BLK>>>();
    k_scatter<<<edgeBlocks, 256>>>(src, dst);

    k_wsplit<<<(3 * 128 * 128 + 255) / 256, 256>>>(Wl1, Wr1, Wl2, Wr2, Wl3, Wr3);

    k_embed<<<warpBlocks, 256>>>(x, W0, b0, g0, be0);
    k_startk<<<nodeBlocks, 256>>>(batch);

    // layer 1: A -> B
    k_agg<<<warpBlocks, 256>>>(hA);
    k_layer<<<tileBlocks, 256>>>(ag, hA, W + 0 * 128 * 256, bl1, g1, be1, nullptr, hB);
    // layer 2: B -> A
    k_agg<<<warpBlocks, 256>>>(hB);
    k_layer<<<tileBlocks, 256>>>(ag, hB, W + 1 * 128 * 256, bl2, g2, be2, nullptr, hA);
    // layer 3: A -> out (fp32 node_embed)
    k_agg<<<warpBlocks, 256>>>(hA);
    k_layer<<<tileBlocks, 256>>>(ag, hA, W + 2 * 128 * 256, bl3, g3, be3, out, nullptr);

    k_poolA<<<BGRAPH * POOL_CH, H>>>(out);
    k_poolB<<<BGRAPH, H>>>(out);
}

// round 13
// speedup vs baseline: 1.4394x; 1.0074x over previous
#include <cuda_runtime.h>
#include <cfloat>
#include <stdint.h>

#define N_NODES 100000
#define N_EDGES 1600000
#define BGRAPH  64
#define DINP    9
#define H       128
#define EPS     1e-5f

#define SCAN_BLK 512
#define SCAN_NB  196   // ceil(100000/512)
#define POOL_CH  16

typedef unsigned u32;

// ---------------- scratch (device globals; no allocation allowed) -----------
// Interleaved bf16 hi/lo storage per node: 128 u32 words.
// word[2p] = hi pair p (ch 2p lo16, 2p+1 hi16); word[2p+1] = lo pair p.
__device__ u32 g_hA[N_NODES * 128];
__device__ u32 g_hB[N_NODES * 128];
__device__ u32 g_ag[N_NODES * 128];
__device__ u32 g_W[3 * 128 * 256];      // per layer [c 128][256 words hi/lo interleaved]
__device__ int g_rowptr[N_NODES + 1];
__device__ int g_col[N_EDGES];
__device__ int g_deg[N_NODES];
__device__ int g_cursor[N_NODES];
__device__ int g_bsum[SCAN_NB];
__device__ int g_start[BGRAPH + 1];
__device__ float g_pp[BGRAPH * POOL_CH * 2 * H];

// ---------------- bf16 helpers ----------------------------------------------
__device__ __forceinline__ u32 bf16rn(float f) {
    u32 u = __float_as_uint(f);
    return (u + 0x7fffu + ((u >> 16) & 1u)) >> 16;
}
__device__ __forceinline__ void bfsplit(float f, u32& hi, u32& lo) {
    hi = bf16rn(f);
    float r = f - __uint_as_float(hi << 16);
    lo = bf16rn(r);
}

#define MMA_BF16(c0,c1,c2,c3,a0,a1,a2,a3,b0,b1) \
    asm volatile("mma.sync.aligned.m16n8k16.row.col.f32.bf16.bf16.f32 " \
        "{%0,%1,%2,%3}, {%4,%5,%6,%7}, {%8,%9}, {%0,%1,%2,%3};\n" \
        : "+f"(c0), "+f"(c1), "+f"(c2), "+f"(c3) \
        : "r"(a0), "r"(a1), "r"(a2), "r"(a3), "r"(b0), "r"(b1))

// ---------------- CSR build -------------------------------------------------
__global__ void k_zero() {
    int i = blockIdx.x * blockDim.x + threadIdx.x;
    if (i < N_NODES) { g_deg[i] = 0; g_cursor[i] = 0; }
}

__global__ void k_deg(const int* __restrict__ dst) {
    int e = blockIdx.x * blockDim.x + threadIdx.x;
    if (e < N_EDGES) atomicAdd(&g_deg[dst[e]], 1);
}

__global__ void k_scan1() {
    __shared__ int sh[SCAN_BLK];
    int t = threadIdx.x;
    int i = blockIdx.x * SCAN_BLK + t;
    int v = (i < N_NODES) ? g_deg[i] : 0;
    sh[t] = v; __syncthreads();
    for (int o = 1; o < SCAN_BLK; o <<= 1) {
        int a = (t >= o) ? sh[t - o] : 0;
        __syncthreads();
        sh[t] += a;
        __syncthreads();
    }
    if (i < N_NODES) g_rowptr[i] = sh[t] - v;
    if (t == SCAN_BLK - 1) g_bsum[blockIdx.x] = sh[t];
}

__global__ void k_scan2() {
    __shared__ int sh[256];
    int t = threadIdx.x;
    int v = (t < SCAN_NB) ? g_bsum[t] : 0;
    sh[t] = v; __syncthreads();
    for (int o = 1; o < 256; o <<= 1) {
        int a = (t >= o) ? sh[t - o] : 0;
        __syncthreads();
        sh[t] += a;
        __syncthreads();
    }
    if (t < SCAN_NB) g_bsum[t] = sh[t] - v;
    if (t == 0) g_rowptr[N_NODES] = N_EDGES;
}

__global__ void k_scan3() {
    int i = blockIdx.x * SCAN_BLK + threadIdx.x;
    if (i < N_NODES) g_rowptr[i] += g_bsum[blockIdx.x];
}

__global__ void k_scatter(const int* __restrict__ src, const int* __restrict__ dst) {
    int e = blockIdx.x * blockDim.x + threadIdx.x;
    if (e < N_EDGES) {
        int d = dst[e];
        int p = atomicAdd(&g_cursor[d], 1);
        g_col[g_rowptr[d] + p] = src[e];
    }
}

// ---------------- weight split (interleaved): W[c][k] = [Wl ; Wr] ------------
__global__ void k_wsplit(const float* __restrict__ Wl1, const float* __restrict__ Wr1,
                         const float* __restrict__ Wl2, const float* __restrict__ Wr2,
                         const float* __restrict__ Wl3, const float* __restrict__ Wr3) {
    int idx = blockIdx.x * blockDim.x + threadIdx.x;   // pair index
    if (idx >= 3 * 128 * 128) return;
    int l = idx / (128 * 128);
    int r = idx % (128 * 128);
    int c = r >> 7;            // 0..127
    int kp = r & 127;          // k-pair
    int k0 = kp * 2;
    const float* Wl = (l == 0) ? Wl1 : (l == 1) ? Wl2 : Wl3;
    const float* Wr = (l == 0) ? Wr1 : (l == 1) ? Wr2 : Wr3;
    float w0 = (k0 < 128) ? Wl[c * 128 + k0] : Wr[c * 128 + k0 - 128];
    float w1 = (k0 + 1 < 128) ? Wl[c * 128 + k0 + 1] : Wr[c * 128 + k0 + 1 - 128];
    u32 h0, l0, h1, l1;
    bfsplit(w0, h0, l0);
    bfsplit(w1, h1, l1);
    size_t base = (size_t)l * 128 * 256 + (size_t)c * 256 + kp * 2;
    *(uint2*)&g_W[base] = make_uint2(h0 | (h1 << 16), l0 | (l1 << 16));
}

// ---------------- node embedder: relu(LN(x @ W0^T + b0)) -> interleaved ------
__global__ void k_embed(const float* __restrict__ x, const float* __restrict__ W0,
                        const float* __restrict__ b0, const float* __restrict__ g0,
                        const float* __restrict__ be0) {
    int gw = (blockIdx.x * blockDim.x + threadIdx.x) >> 5;
    int lane = threadIdx.x & 31;
    if (gw >= N_NODES) return;
    float xd = (lane < DINP) ? x[gw * DINP + lane] : 0.f;
    float xs[DINP];
#pragma unroll
    for (int d = 0; d < DINP; d++) xs[d] = __shfl_sync(0xffffffffu, xd, d);
    float o[4];
#pragma unroll
    for (int j = 0; j < 4; j++) {
        int c = lane * 4 + j;
        float acc = b0[c];
#pragma unroll
        for (int d = 0; d < DINP; d++) acc = fmaf(xs[d], W0[c * DINP + d], acc);
        o[j] = acc;
    }
    float s1 = o[0] + o[1] + o[2] + o[3];
    float s2 = o[0]*o[0] + o[1]*o[1] + o[2]*o[2] + o[3]*o[3];
#pragma unroll
    for (int off = 16; off; off >>= 1) {
        s1 += __shfl_xor_sync(0xffffffffu, s1, off);
        s2 += __shfl_xor_sync(0xffffffffu, s2, off);
    }
    float m  = s1 * (1.f / H);
    float var = fmaxf(s2 * (1.f / H) - m * m, 0.f);
    float rs = rsqrtf(var + EPS);
    u32 hb[4], lb[4];
#pragma unroll
    for (int j = 0; j < 4; j++) {
        int c = lane * 4 + j;
        float v = fmaxf((o[j] - m) * rs * g0[c] + be0[c], 0.f);
        bfsplit(v, hb[j], lb[j]);
    }
    size_t base = (size_t)gw * 128 + lane * 4;
    *(uint4*)&g_hA[base] = make_uint4(hb[0] | (hb[1] << 16), lb[0] | (lb[1] << 16),
                                      hb[2] | (hb[3] << 16), lb[2] | (lb[3] << 16));
}

// ---------------- mean aggregation: warp per node ----------------------------
__global__ void k_agg(const u32* __restrict__ h) {
    int gw = (blockIdx.x * blockDim.x + threadIdx.x) >> 5;
    int lane = threadIdx.x & 31;
    if (gw >= N_NODES) return;
    int s = g_rowptr[gw], e = g_rowptr[gw + 1];
    int lane4 = lane * 4;
    float a0 = 0.f, a1 = 0.f, a2 = 0.f, a3 = 0.f;
    float b0 = 0.f, b1 = 0.f, b2 = 0.f, b3 = 0.f;
    int p = s;
    for (; p + 1 < e; p += 2) {
        int sn0 = __ldg(&g_col[p]);
        int sn1 = __ldg(&g_col[p + 1]);
        uint4 w0 = *(const uint4*)&h[(size_t)sn0 * 128 + lane4];
        uint4 w1 = *(const uint4*)&h[(size_t)sn1 * 128 + lane4];
        a0 += __uint_as_float(w0.x << 16) + __uint_as_float(w0.y << 16);
        a1 += __uint_as_float(w0.x & 0xffff0000u) + __uint_as_float(w0.y & 0xffff0000u);
        a2 += __uint_as_float(w0.z << 16) + __uint_as_float(w0.w << 16);
        a3 += __uint_as_float(w0.z & 0xffff0000u) + __uint_as_float(w0.w & 0xffff0000u);
        b0 += __uint_as_float(w1.x << 16) + __uint_as_float(w1.y << 16);
        b1 += __uint_as_float(w1.x & 0xffff0000u) + __uint_as_float(w1.y & 0xffff0000u);
        b2 += __uint_as_float(w1.z << 16) + __uint_as_float(w1.w << 16);
        b3 += __uint_as_float(w1.z & 0xffff0000u) + __uint_as_float(w1.w & 0xffff0000u);
    }
    if (p < e) {
        int sn = __ldg(&g_col[p]);
        uint4 w = *(const uint4*)&h[(size_t)sn * 128 + lane4];
        a0 += __uint_as_float(w.x << 16) + __uint_as_float(w.y << 16);
        a1 += __uint_as_float(w.x & 0xffff0000u) + __uint_as_float(w.y & 0xffff0000u);
        a2 += __uint_as_float(w.z << 16) + __uint_as_float(w.w << 16);
        a3 += __uint_as_float(w.z & 0xffff0000u) + __uint_as_float(w.w & 0xffff0000u);
    }
    float inv = 1.f / fmaxf((float)(e - s), 1.f);
    a0 = (a0 + b0) * inv; a1 = (a1 + b1) * inv;
    a2 = (a2 + b2) * inv; a3 = (a3 + b3) * inv;
    u32 h0, l0, h1, l1, h2, l2, h3, l3;
    bfsplit(a0, h0, l0); bfsplit(a1, h1, l1);
    bfsplit(a2, h2, l2); bfsplit(a3, h3, l3);
    *(uint4*)&g_ag[(size_t)gw * 128 + lane4] =
        make_uint4(h0 | (h1 << 16), l0 | (l1 << 16), h2 | (h3 << 16), l2 | (l3 << 16));
}

// ---------------- tensor-core layer: bf16x3 MMA + LayerNorm + ReLU ----------
// Software-pipelined: chunk c+1 prefetched into registers while chunk c's MMAs
// issue; STS after barrier. Single smem buffer (static < 48 KB).
__global__ void __launch_bounds__(256, 2) k_layer(
    const u32* __restrict__ ag, const u32* __restrict__ h,
    const u32* __restrict__ W,
    const float* __restrict__ bl, const float* __restrict__ gg,
    const float* __restrict__ be,
    float* __restrict__ outF, u32* __restrict__ outI)
{
    __shared__ __align__(16) u32 AsHi[128 * 16];
    __shared__ __align__(16) u32 AsLo[128 * 16];
    __shared__ __align__(16) u32 WsHi[128 * 16];
    __shared__ __align__(16) u32 WsLo[128 * 16];
    __shared__ float sBl[128], sGg[128], sBe[128];

    int t = threadIdx.x;
    int lane = t & 31;
    int wid = t >> 5;
    int g  = lane >> 2;     // 0..7
    int t2 = lane & 3;      // 0..3
    int m0 = wid * 16;
    int nodeBase = blockIdx.x * 128;

    if (t < 128) { sBl[t] = bl[t]; sGg[t] = gg[t]; sBe[t] = be[t]; }

    // precompute per-it staging indices (invariant across chunks)
    int sRow[8], sJ32[8], sIdx[8];
#pragma unroll
    for (int it = 0; it < 8; it++) {
        int i = it * 256 + t;
        int row = i >> 4;
        int j32 = i & 15;
        int blk = j32 >> 3, j = j32 & 7;
        int pj = (j < 4) ? (2 * j) : (2 * j - 7);
        sRow[it] = row;
        sJ32[it] = j32;
        sIdx[it] = (row * 16 + blk * 8 + pj) ^ (((row >> 1) & 1) << 3);
    }

    float acc[16][4];
#pragma unroll
    for (int nt = 0; nt < 16; nt++)
#pragma unroll
        for (int j = 0; j < 4; j++) acc[nt][j] = 0.f;

    // ---- prologue: stage chunk 0 (from ag) directly ----
#pragma unroll
    for (int it = 0; it < 8; it++) {
        int gnode = nodeBase + sRow[it];
        uint2 v = make_uint2(0u, 0u);
        if (gnode < N_NODES)
            v = *(const uint2*)&ag[(size_t)gnode * 128 + 2 * sJ32[it]];
        AsHi[sIdx[it]] = v.x; AsLo[sIdx[it]] = v.y;
        uint2 w = *(const uint2*)&W[(size_t)sRow[it] * 256 + 2 * sJ32[it]];
        WsHi[sIdx[it]] = w.x; WsLo[sIdx[it]] = w.y;
    }
    __syncthreads();

#pragma unroll 1
    for (int kk = 0; kk < 256; kk += 32) {
        // ---- prefetch chunk kk+32 into registers (latency hides under MMAs) ----
        uint2 va[8], vw[8];
        bool have = (kk + 32) < 256;
        if (have) {
            int kn = kk + 32;
            const u32* feat = (kn < 128) ? ag : h;
            int koff = (kn < 128) ? kn : kn - 128;
#pragma unroll
            for (int it = 0; it < 8; it++) {
                int gnode = nodeBase + sRow[it];
                va[it] = make_uint2(0u, 0u);
                if (gnode < N_NODES)
                    va[it] = *(const uint2*)&feat[(size_t)gnode * 128 + koff + 2 * sJ32[it]];
                vw[it] = *(const uint2*)&W[(size_t)sRow[it] * 256 + kn + 2 * sJ32[it]];
            }
        }

        // ---- compute on current buffer ----
#pragma unroll
        for (int blk = 0; blk < 2; blk++) {
            int rA = m0 + g, rB = m0 + g + 8;
            int iA = (rA * 16 + blk * 8 + 2 * t2) ^ (((rA >> 1) & 1) << 3);
            int iB = (rB * 16 + blk * 8 + 2 * t2) ^ (((rB >> 1) & 1) << 3);
            uint2 a02h = *(const uint2*)&AsHi[iA];
            uint2 a13h = *(const uint2*)&AsHi[iB];
            uint2 a02l = *(const uint2*)&AsLo[iA];
            uint2 a13l = *(const uint2*)&AsLo[iB];
#pragma unroll
            for (int nt = 0; nt < 16; nt++) {
                int c = nt * 8 + g;
                int iW = (c * 16 + blk * 8 + 2 * t2) ^ (((c >> 1) & 1) << 3);
                uint2 bh = *(const uint2*)&WsHi[iW];
                uint2 blo = *(const uint2*)&WsLo[iW];
                MMA_BF16(acc[nt][0], acc[nt][1], acc[nt][2], acc[nt][3],
                         a02h.x, a13h.x, a02h.y, a13h.y, bh.x, bh.y);
                MMA_BF16(acc[nt][0], acc[nt][1], acc[nt][2], acc[nt][3],
                         a02h.x, a13h.x, a02h.y, a13h.y, blo.x, blo.y);
                MMA_BF16(acc[nt][0], acc[nt][1], acc[nt][2], acc[nt][3],
                         a02l.x, a13l.x, a02l.y, a13l.y, bh.x, bh.y);
            }
        }
        __syncthreads();
        if (have) {
#pragma unroll
            for (int it = 0; it < 8; it++) {
                AsHi[sIdx[it]] = va[it].x; AsLo[sIdx[it]] = va[it].y;
                WsHi[sIdx[it]] = vw[it].x; WsLo[sIdx[it]] = vw[it].y;
            }
            __syncthreads();
        }
    }

    // ---- epilogue ----
    float sA1 = 0.f, sA2 = 0.f, sB1 = 0.f, sB2 = 0.f;
#pragma unroll
    for (int nt = 0; nt < 16; nt++) {
        int c0 = nt * 8 + 2 * t2;
        float b0 = sBl[c0], b1 = sBl[c0 + 1];
        float va0 = acc[nt][0] + b0, va1 = acc[nt][1] + b1;
        float vb0 = acc[nt][2] + b0, vb1 = acc[nt][3] + b1;
        sA1 += va0 + va1; sA2 += va0 * va0 + va1 * va1;
        sB1 += vb0 + vb1; sB2 += vb0 * vb0 + vb1 * vb1;
    }
#pragma unroll
    for (int off = 1; off <= 2; off <<= 1) {
        sA1 += __shfl_xor_sync(0xffffffffu, sA1, off);
        sA2 += __shfl_xor_sync(0xffffffffu, sA2, off);
        sB1 += __shfl_xor_sync(0xffffffffu, sB1, off);
        sB2 += __shfl_xor_sync(0xffffffffu, sB2, off);
    }
    float mA = sA1 * (1.f / H);
    float vA = fmaxf(sA2 * (1.f / H) - mA * mA, 0.f);
    float rsA = rsqrtf(vA + EPS);
    float mB = sB1 * (1.f / H);
    float vB = fmaxf(sB2 * (1.f / H) - mB * mB, 0.f);
    float rsB = rsqrtf(vB + EPS);

    int gA = nodeBase + m0 + g;
    int gB = gA + 8;
    bool wA = gA < N_NODES, wB = gB < N_NODES;

#pragma unroll
    for (int nt = 0; nt < 16; nt++) {
        int c0 = nt * 8 + 2 * t2;
        float b0 = sBl[c0], b1 = sBl[c0 + 1];
        float gg0 = sGg[c0], gg1 = sGg[c0 + 1];
        float be0 = sBe[c0], be1 = sBe[c0 + 1];
        float oa0 = fmaxf((acc[nt][0] + b0 - mA) * rsA * gg0 + be0, 0.f);
        float oa1 = fmaxf((acc[nt][1] + b1 - mA) * rsA * gg1 + be1, 0.f);
        float ob0 = fmaxf((acc[nt][2] + b0 - mB) * rsB * gg0 + be0, 0.f);
        float ob1 = fmaxf((acc[nt][3] + b1 - mB) * rsB * gg1 + be1, 0.f);
        if (outF) {
            if (wA) *(float2*)&outF[(size_t)gA * 128 + c0] = make_float2(oa0, oa1);
            if (wB) *(float2*)&outF[(size_t)gB * 128 + c0] = make_float2(ob0, ob1);
        } else {
            u32 h0, l0, h1, l1;
            if (wA) {
                bfsplit(oa0, h0, l0); bfsplit(oa1, h1, l1);
                *(uint2*)&outI[(size_t)gA * 128 + c0] =
                    make_uint2(h0 | (h1 << 16), l0 | (l1 << 16));
            }
            if (wB) {
                bfsplit(ob0, h0, l0); bfsplit(ob1, h1, l1);
                *(uint2*)&outI[(size_t)gB * 128 + c0] =
                    make_uint2(h0 | (h1 << 16), l0 | (l1 << 16));
            }
        }
    }
}

// ---------------- pooling (two-stage) ---------------------------------------
__global__ void k_startk(const int* __restrict__ batch) {
    int i = blockIdx.x * blockDim.x + threadIdx.x;
    if (i >= N_NODES) return;
    int b  = batch[i];
    int bp = (i == 0) ? -1 : batch[i - 1];
    for (int g = bp + 1; g <= b; g++) g_start[g] = i;
    if (i == N_NODES - 1)
        for (int g = b + 1; g <= BGRAPH; g++) g_start[g] = N_NODES;
}

__global__ void k_poolA(const float* __restrict__ ne) {
    int b  = blockIdx.x / POOL_CH;
    int ch = blockIdx.x % POOL_CH;
    int c  = threadIdx.x;
    int s = g_start[b], e = g_start[b + 1];
    int len = e - s;
    int cs = s + (int)(((long long)len * ch) / POOL_CH);
    int ce = s + (int)(((long long)len * (ch + 1)) / POOL_CH);
    float sum = 0.f, mx = -FLT_MAX;
    for (int n = cs; n < ce; n++) {
        float v = ne[(size_t)n * H + c];
        sum += v;
        mx = fmaxf(mx, v);
    }
    size_t base = ((size_t)(b * POOL_CH + ch)) * 2 * H;
    g_pp[base + c]     = sum;
    g_pp[base + H + c] = mx;
}

__global__ void k_poolB(float* __restrict__ out) {
    int b = blockIdx.x;
    int c = threadIdx.x;
    int s = g_start[b], e = g_start[b + 1];
    float sum = 0.f, mx = -FLT_MAX;
#pragma unroll
    for (int ch = 0; ch < POOL_CH; ch++) {
        size_t base = ((size_t)(b * POOL_CH + ch)) * 2 * H;
        sum += g_pp[base + c];
        mx = fmaxf(mx, g_pp[base + H + c]);
    }
    float cnt = (float)(e - s);
    size_t gbase = (size_t)N_NODES * H + (size_t)b * 2 * H;
    out[gbase + c]     = sum / fmaxf(cnt, 1.f);
    out[gbase + H + c] = mx;
}

// ---------------- launch ----------------------------------------------------
extern "C" void kernel_launch(void* const* d_in, const int* in_sizes, int n_in,
                              void* d_out, int out_size) {
    const float* x     = (const float*)d_in[0];
    const int*   ei    = (const int*)  d_in[1];
    const int*   batch = (const int*)  d_in[2];
    const float* W0  = (const float*)d_in[3];
    const float* b0  = (const float*)d_in[4];
    const float* g0  = (const float*)d_in[5];
    const float* be0 = (const float*)d_in[6];
    const float* Wl1 = (const float*)d_in[7];
    const float* bl1 = (const float*)d_in[8];
    const float* Wr1 = (const float*)d_in[9];
    const float* g1  = (const float*)d_in[10];
    const float* be1 = (const float*)d_in[11];
    const float* Wl2 = (const float*)d_in[12];
    const float* bl2 = (const float*)d_in[13];
    const float* Wr2 = (const float*)d_in[14];
    const float* g2  = (const float*)d_in[15];
    const float* be2 = (const float*)d_in[16];
    const float* Wl3 = (const float*)d_in[17];
    const float* bl3 = (const float*)d_in[18];
    const float* Wr3 = (const float*)d_in[19];
    const float* g3  = (const float*)d_in[20];
    const float* be3 = (const float*)d_in[21];

    const int* src = ei;
    const int* dst = ei + N_EDGES;
    float* out = (float*)d_out;

    u32 *hA, *hB, *ag, *W;
    cudaGetSymbolAddress((void**)&hA, g_hA);
    cudaGetSymbolAddress((void**)&hB, g_hB);
    cudaGetSymbolAddress((void**)&ag, g_ag);
    cudaGetSymbolAddress((void**)&W, g_W);

    const int nodeBlocks = (N_NODES + 255) / 256;
    const int edgeBlocks = (N_EDGES + 255) / 256;
    const int warpBlocks = (N_NODES + 7) / 8;          // 8 warps/block
    const int tileBlocks = (N_NODES + 127) / 128;      // 782

    // CSR build (every launch — caching is forbidden)
    k_zero<<<nodeBlocks, 256>>>();
    k_deg<<<edgeBlocks, 256>>>(dst);
    k_scan1<<<SCAN_NB, SCAN_BLK>>>();
    k_scan2<<<1, 256>>>();
    k_scan3<<<SCAN_NB, SCAN_BLK>>>();
    k_scatter<<<edgeBlocks, 256>>>(src, dst);

    k_wsplit<<<(3 * 128 * 128 + 255) / 256, 256>>>(Wl1, Wr1, Wl2, Wr2, Wl3, Wr3);

    k_embed<<<warpBlocks, 256>>>(x, W0, b0, g0, be0);
    k_startk<<<nodeBlocks, 256>>>(batch);

    // layer 1: A -> B
    k_agg<<<warpBlocks, 256>>>(hA);
    k_layer<<<tileBlocks, 256>>>(ag, hA, W + 0 * 128 * 256, bl1, g1, be1, nullptr, hB);
    // layer 2: B -> A
    k_agg<<<warpBlocks, 256>>>(hB);
    k_layer<<<tileBlocks, 256>>>(ag, hB, W + 1 * 128 * 256, bl2, g2, be2, nullptr, hA);
    // layer 3: A -> out (fp32 node_embed)
    k_agg<<<warpBlocks, 256>>>(hA);
    k_layer<<<tileBlocks, 256>>>(ag, hA, W + 2 * 128 * 256, bl3, g3, be3, out, nullptr);

    k_poolA<<<BGRAPH * POOL_CH, H>>>(out);
    k_poolB<<<BGRAPH, H>>>(out);
}